// round 6
// baseline (speedup 1.0000x reference)
#include <cuda_runtime.h>
#include <cstdint>
#include <math.h>

#define MAXN 500000
#define MAXV 50000

// ---- scratch (static __device__ arrays; allocation-free) ----
__device__ __align__(128) float g_pf2[(size_t)MAXN * 128];
__device__ __align__(128) float g_vox[(size_t)MAXV * 128];
__device__ __align__(128) float g_voxf[(size_t)MAXV * 128];
__device__ __align__(128) float g_vox2[(size_t)MAXV * 256];
__device__ __align__(128) float g_w3t[65536];   // w3 tf32
__device__ __align__(128) float g_w4t[65536];   // w4 tf32
__device__ __align__(128) float g_wvt[65536];   // wv2 tf32

__device__ __forceinline__ void amax_pos(float* addr, float v) {
    if (v > 0.f) atomicMax((int*)addr, __float_as_int(v));
}

__device__ __forceinline__ uint32_t f2tf32(float f) {
    uint32_t r;
    asm("cvt.rna.tf32.f32 %0, %1;" : "=r"(r) : "f"(f));
    return r;
}
__device__ __forceinline__ float tf32f(float f) { return __uint_as_float(f2tf32(f)); }

__device__ __forceinline__ uint32_t smem_u32(const void* p) {
    return (uint32_t)__cvta_generic_to_shared(p);
}
__device__ __forceinline__ void cp_async16(uint32_t dst, const void* src) {
    asm volatile("cp.async.ca.shared.global [%0], [%1], 16;" :: "r"(dst), "l"(src));
}
#define CP_COMMIT() asm volatile("cp.async.commit_group;" ::: "memory")
#define CP_WAIT0()  asm volatile("cp.async.wait_group 0;" ::: "memory")

// ---------------------------------------------------------------------------
__global__ void zero_k(int na, int nb) {
    int i = blockIdx.x * blockDim.x + threadIdx.x;
    int stride = gridDim.x * blockDim.x;
    for (int j = i; j < nb; j += stride) {
        if (j < na) g_vox[j] = 0.f;
        g_vox2[j] = 0.f;
    }
}

__global__ void prep_tf32(const float* __restrict__ w, float* __restrict__ dst) {
    int i = blockIdx.x * blockDim.x + threadIdx.x;
    if (i < 65536) dst[i] = __uint_as_float(f2tf32(w[i]));
}

// ---------------------------------------------------------------------------
// warp micro-GEMM helper: [16x64]@[64x32], A stride 68, B stride 40
// ---------------------------------------------------------------------------
__device__ __forceinline__ void gemm64x32(const float* __restrict__ As,
                                          const float* __restrict__ Bt,
                                          int wr, int g, int t4, float acc[4][4]) {
#pragma unroll
    for (int k8 = 0; k8 < 8; k8++) {
        const float* ap = As + (wr + g) * 68 + k8 * 8 + t4;
        uint32_t a0 = __float_as_uint(ap[0]);
        uint32_t a1 = __float_as_uint(ap[8 * 68]);
        uint32_t a2 = __float_as_uint(ap[4]);
        uint32_t a3 = __float_as_uint(ap[8 * 68 + 4]);
#pragma unroll
        for (int nt = 0; nt < 4; nt++) {
            const float* bp = Bt + (k8 * 8 + t4) * 40 + nt * 8 + g;
            uint32_t b0 = __float_as_uint(bp[0]);
            uint32_t b1 = __float_as_uint(bp[4 * 40]);
            asm volatile(
                "mma.sync.aligned.m16n8k8.row.col.f32.tf32.tf32.f32 "
                "{%0,%1,%2,%3},{%4,%5,%6,%7},{%8,%9},{%0,%1,%2,%3};"
                : "+f"(acc[nt][0]), "+f"(acc[nt][1]), "+f"(acc[nt][2]), "+f"(acc[nt][3])
                : "r"(a0), "r"(a1), "r"(a2), "r"(a3), "r"(b0), "r"(b1));
        }
    }
}

// ---------------------------------------------------------------------------
// Stage A via mma.sync tf32 (unchanged)
// ---------------------------------------------------------------------------
#define SAM_THREADS 256
#define SAM_SMEM (28288 * 4)

__global__ __launch_bounds__(SAM_THREADS) void stage_a_mma(
    const float* __restrict__ inp, const int* __restrict__ vidx, int n,
    const float* __restrict__ w1x, const float* __restrict__ b1x,
    const float* __restrict__ w2x, const float* __restrict__ b2x,
    const float* __restrict__ w1r, const float* __restrict__ b1r,
    const float* __restrict__ w2r, const float* __restrict__ b2r,
    const float* __restrict__ wax, const float* __restrict__ bax,
    const float* __restrict__ war, const float* __restrict__ bar)
{
    extern __shared__ float sm[];
    float* sW = sm;
    float* sB = sm + 512;
    float* sA = sm + 10752;
    float* sC = sm + 19456;
    int*   svx = (int*)(sm + 28160);

    int t = threadIdx.x;
    int lane = t & 31, w = t >> 5;
    int g = lane >> 2, t4 = lane & 3;
    int wr = 16 * w;
    int row0 = blockIdx.x * 128;

    for (int i = t; i < 192; i += SAM_THREADS) { sW[i] = w1x[i]; sW[256 + i] = w1r[i]; }
    for (int i = t; i < 64; i += SAM_THREADS)  { sW[192 + i] = b1x[i]; sW[448 + i] = b1r[i]; }
    {
        const float* wsrc[4] = {w2x, w2r, wax, war};
#pragma unroll
        for (int a = 0; a < 4; a++) {
            float* dst = sB + a * 2560;
            const float* s = wsrc[a];
            for (int i = t; i < 2048; i += SAM_THREADS) {
                int k = i >> 5, c = i & 31;
                dst[k * 40 + c] = __uint_as_float(f2tf32(s[i]));
            }
        }
    }
    __syncthreads();

    int p = t >> 1, half = t & 1;
    int cp = min(row0 + p, n - 1);
    if (half == 0) svx[p] = vidx[cp];
    float i0 = inp[(size_t)cp * 6 + 0], i1 = inp[(size_t)cp * 6 + 1], i2 = inp[(size_t)cp * 6 + 2];
    float i3 = inp[(size_t)cp * 6 + 3], i4 = inp[(size_t)cp * 6 + 4], i5 = inp[(size_t)cp * 6 + 5];

    {
        const float* W = sW; const float* B = sW + 192;
        int ob = half * 32;
#pragma unroll 8
        for (int o = 0; o < 32; o++) {
            int oo = ob + o;
            float a = B[oo] + i0 * W[oo] + i1 * W[64 + oo] + i2 * W[128 + oo];
            sA[p * 68 + oo] = tf32f(fmaxf(a, 0.f));
        }
    }
    __syncwarp();

    float fx[4][4];
#pragma unroll
    for (int nt = 0; nt < 4; nt++)
#pragma unroll
        for (int j = 0; j < 4; j++) fx[nt][j] = 0.f;
    gemm64x32(sA, sB, wr, g, t4, fx);
    __syncwarp();

#pragma unroll
    for (int nt = 0; nt < 4; nt++) {
        int c = nt * 8 + 2 * t4;
        float bc0 = __ldg(b2x + c), bc1 = __ldg(b2x + c + 1);
        fx[nt][0] = fmaxf(fx[nt][0] + bc0, 0.f);
        fx[nt][1] = fmaxf(fx[nt][1] + bc1, 0.f);
        fx[nt][2] = fmaxf(fx[nt][2] + bc0, 0.f);
        fx[nt][3] = fmaxf(fx[nt][3] + bc1, 0.f);
        int r = wr + g;
        *(float2*)(sC + r * 68 + c) = make_float2(tf32f(fx[nt][0]), tf32f(fx[nt][1]));
        *(float2*)(sC + (r + 8) * 68 + c) = make_float2(tf32f(fx[nt][2]), tf32f(fx[nt][3]));
    }
    {
        const float* W = sW + 256; const float* B = sW + 448;
        int ob = half * 32;
#pragma unroll 8
        for (int o = 0; o < 32; o++) {
            int oo = ob + o;
            float a = B[oo] + i3 * W[oo] + i4 * W[64 + oo] + i5 * W[128 + oo];
            sA[p * 68 + oo] = tf32f(fmaxf(a, 0.f));
        }
    }
    __syncwarp();

    float fr[4][4];
#pragma unroll
    for (int nt = 0; nt < 4; nt++)
#pragma unroll
        for (int j = 0; j < 4; j++) fr[nt][j] = 0.f;
    gemm64x32(sA, sB + 2560, wr, g, t4, fr);
#pragma unroll
    for (int nt = 0; nt < 4; nt++) {
        int c = nt * 8 + 2 * t4;
        float bc0 = __ldg(b2r + c), bc1 = __ldg(b2r + c + 1);
        fr[nt][0] = fmaxf(fr[nt][0] + bc0, 0.f);
        fr[nt][1] = fmaxf(fr[nt][1] + bc1, 0.f);
        fr[nt][2] = fmaxf(fr[nt][2] + bc0, 0.f);
        fr[nt][3] = fmaxf(fr[nt][3] + bc1, 0.f);
        int r = wr + g;
        *(float2*)(sC + r * 68 + 32 + c) = make_float2(tf32f(fr[nt][0]), tf32f(fr[nt][1]));
        *(float2*)(sC + (r + 8) * 68 + 32 + c) = make_float2(tf32f(fr[nt][2]), tf32f(fr[nt][3]));
    }
    __syncwarp();

    float ax[4][4], ar[4][4];
#pragma unroll
    for (int nt = 0; nt < 4; nt++)
#pragma unroll
        for (int j = 0; j < 4; j++) { ax[nt][j] = 0.f; ar[nt][j] = 0.f; }
    gemm64x32(sC, sB + 2 * 2560, wr, g, t4, ax);
    gemm64x32(sC, sB + 3 * 2560, wr, g, t4, ar);

#pragma unroll
    for (int h2 = 0; h2 < 2; h2++) {
        int r = wr + g + 8 * h2;
        int pt = row0 + r;
        if (pt < n) {
            int vr = svx[r];
            float* pfr = g_pf2 + (size_t)pt * 128;
            float* vxr = g_vox + (size_t)vr * 128;
#pragma unroll
            for (int nt = 0; nt < 4; nt++) {
                int c = nt * 8 + 2 * t4;
                int j0 = 2 * h2, j1 = 2 * h2 + 1;
                float axa = ax[nt][j0] + __ldg(bax + c);
                float axb = ax[nt][j1] + __ldg(bax + c + 1);
                float ara = ar[nt][j0] + __ldg(bar + c);
                float arb = ar[nt][j1] + __ldg(bar + c + 1);
                float sxa = 1.f / (1.f + __expf(-axa));
                float sxb = 1.f / (1.f + __expf(-axb));
                float sra = 1.f / (1.f + __expf(-ara));
                float srb = 1.f / (1.f + __expf(-arb));
                float fxa = fx[nt][j0], fxb = fx[nt][j1];
                float fra = fr[nt][j0], frb = fr[nt][j1];
                float v1a = fxa * sxa, v1b = fxb * sxb;
                float v3a = fra * sra, v3b = frb * srb;
                *(float2*)(pfr + c)      = make_float2(fxa, fxb);
                *(float2*)(pfr + 32 + c) = make_float2(v1a, v1b);
                *(float2*)(pfr + 64 + c) = make_float2(fra, frb);
                *(float2*)(pfr + 96 + c) = make_float2(v3a, v3b);
                amax_pos(vxr + c, fxa);        amax_pos(vxr + c + 1, fxb);
                amax_pos(vxr + 32 + c, v1a);   amax_pos(vxr + 33 + c, v1b);
                amax_pos(vxr + 64 + c, fra);   amax_pos(vxr + 65 + c, frb);
                amax_pos(vxr + 96 + c, v3a);   amax_pos(vxr + 97 + c, v3b);
            }
        }
    }
}

// ---------------------------------------------------------------------------
// Generic tiled fp32 GEMM (kept for the small wv1 layer)
// ---------------------------------------------------------------------------
template <int K, int NC>
__global__ __launch_bounds__(256) void gemm_relu(
    const float* __restrict__ A, const float* __restrict__ W,
    const float* __restrict__ bias, float* __restrict__ out, int M)
{
    extern __shared__ float sm[];
    float* a_s = sm;
    float* b_s = sm + K * 68;
    const int TN = NC / 32;
    int t = threadIdx.x;
    int c = t & 31, r = t >> 5;
    int row0 = blockIdx.x * 64;
    {
        int row = t >> 2, q = t & 3;
        int gr = min(row0 + row, M - 1);
        const float4* src = (const float4*)(A + (size_t)gr * K + q * (K / 4));
#pragma unroll
        for (int u = 0; u < K / 16; ++u) {
            float4 v = src[u];
            int k = q * (K / 4) + 4 * u;
            a_s[(k + 0) * 68 + row] = v.x;
            a_s[(k + 1) * 68 + row] = v.y;
            a_s[(k + 2) * 68 + row] = v.z;
            a_s[(k + 3) * 68 + row] = v.w;
        }
    }
    float acc[8][TN];
#pragma unroll
    for (int i = 0; i < 8; i++)
#pragma unroll
        for (int j = 0; j < TN; j++) acc[i][j] = 0.f;
    for (int kc = 0; kc < K / 32; ++kc) {
        {
            const float4* ws = (const float4*)(W + (size_t)(kc * 32 + (t >> 3)) * NC + (t & 7) * (NC / 8));
            float4* wd = (float4*)(b_s + (t >> 3) * NC + (t & 7) * (NC / 8));
#pragma unroll
            for (int q = 0; q < NC / 32; q++) wd[q] = ws[q];
        }
        __syncthreads();
#pragma unroll
        for (int k = 0; k < 32; k++) {
            const float* ar = a_s + (kc * 32 + k) * 68 + 8 * r;
            float4 a0 = *(const float4*)ar;
            float4 a1 = *(const float4*)(ar + 4);
            float av[8] = {a0.x, a0.y, a0.z, a0.w, a1.x, a1.y, a1.z, a1.w};
            const float* br = b_s + k * NC + 4 * c;
            float bv[TN];
            {
                float4 b0 = *(const float4*)br;
                bv[0] = b0.x; bv[1] = b0.y; bv[2] = b0.z; bv[3] = b0.w;
            }
            if (TN == 8) {
                float4 b1v = *(const float4*)(br + NC / 2);
                bv[4] = b1v.x; bv[5] = b1v.y; bv[6] = b1v.z; bv[7] = b1v.w;
            }
#pragma unroll
            for (int i = 0; i < 8; i++)
#pragma unroll
                for (int j = 0; j < TN; j++) acc[i][j] += av[i] * bv[j];
        }
        __syncthreads();
    }
    float bb[TN];
#pragma unroll
    for (int j = 0; j < TN; j++) {
        int col = (j < 4) ? 4 * c + j : NC / 2 + 4 * c + (j - 4);
        bb[j] = bias[col];
    }
#pragma unroll
    for (int i = 0; i < 8; i++) {
        int row = row0 + 8 * r + i;
        if (row < M) {
#pragma unroll
            for (int j = 0; j < TN; j++) {
                int col = (j < 4) ? 4 * c + j : NC / 2 + 4 * c + (j - 4);
                out[(size_t)row * NC + col] = fmaxf(acc[i][j] + bb[j], 0.f);
            }
        }
    }
}

// ---------------------------------------------------------------------------
// Stage C v3: cp.async double-buffered weight stream, ONE barrier per k-chunk.
// 128-point tiles, 512 threads (16 warps, 4m x 4n), m16n8k8 tf32.
// ---------------------------------------------------------------------------
#define SA_ST 260
#define SB_ST 264
#define SC_SMEM ((128 * SA_ST + 2 * 32 * SB_ST + 128) * 4)

// async-load one 32x256 weight chunk into sB buffer (4 x cp.async per thread)
__device__ __forceinline__ void ldB_async(const float* __restrict__ ws,
                                          uint32_t sBu, int t) {
#pragma unroll
    for (int i = 0; i < 4; i++) {
        int e = t + i * 512;                  // float4 index within chunk
        int k = e >> 6, n4 = e & 63;
        cp_async16(sBu + (uint32_t)(k * SB_ST + n4 * 4) * 4u,
                   (const float4*)ws + e);
    }
}

__device__ __forceinline__ void mma_chunk(const float* __restrict__ sA,
                                          const float* __restrict__ bufB,
                                          int kc, int wm, int wn, int g, int t4,
                                          float acc[2][8][4]) {
#pragma unroll
    for (int k8 = 0; k8 < 4; k8++) {
        int k0 = kc * 32 + k8 * 8;
        uint32_t a[2][4];
#pragma unroll
        for (int mt = 0; mt < 2; mt++) {
            const float* ap = sA + (wm * 32 + mt * 16 + g) * SA_ST + k0 + t4;
            a[mt][0] = __float_as_uint(ap[0]);
            a[mt][1] = __float_as_uint(ap[8 * SA_ST]);
            a[mt][2] = __float_as_uint(ap[4]);
            a[mt][3] = __float_as_uint(ap[8 * SA_ST + 4]);
        }
#pragma unroll
        for (int nt = 0; nt < 8; nt++) {
            const float* bp = bufB + (k8 * 8 + t4) * SB_ST + wn * 64 + nt * 8 + g;
            uint32_t b0 = __float_as_uint(bp[0]);
            uint32_t b1 = __float_as_uint(bp[4 * SB_ST]);
#pragma unroll
            for (int mt = 0; mt < 2; mt++) {
                asm volatile(
                    "mma.sync.aligned.m16n8k8.row.col.f32.tf32.tf32.f32 "
                    "{%0,%1,%2,%3},{%4,%5,%6,%7},{%8,%9},{%0,%1,%2,%3};"
                    : "+f"(acc[mt][nt][0]), "+f"(acc[mt][nt][1]),
                      "+f"(acc[mt][nt][2]), "+f"(acc[mt][nt][3])
                    : "r"(a[mt][0]), "r"(a[mt][1]), "r"(a[mt][2]), "r"(a[mt][3]),
                      "r"(b0), "r"(b1));
            }
        }
    }
}

__global__ __launch_bounds__(512) void stage_c_mma(
    const int* __restrict__ vidx, int n,
    const float* __restrict__ b3, const float* __restrict__ b4)
{
    extern __shared__ float sm[];
    float* sA = sm;                          // [128][SA_ST]
    float* sB = sm + 128 * SA_ST;            // [2][32][SB_ST]
    int* svx = (int*)(sB + 2 * 32 * SB_ST);  // [128]
    uint32_t sBu = smem_u32(sB);

    int t = threadIdx.x;
    int lane = t & 31, wid = t >> 5;
    int g = lane >> 2, t4 = lane & 3;
    int wm = wid & 3, wn = wid >> 2;
    int row0 = blockIdx.x * 128;
    const uint32_t bufu[2] = {sBu, sBu + 32u * SB_ST * 4u};

    // prologue: start async load of w3 chunk 0 BEFORE the gather
    ldB_async((const float*)g_w3t, bufu[0], t);
    CP_COMMIT();

    // ---- gather pf3 = [voxf[vidx[p]], pf2[p]] into sA as tf32 ----
    {
        int p = t >> 2, q = t & 3;
        int pt = row0 + p;
        int cp = min(pt, n - 1);
        int vr = vidx[cp];
        if (q == 0) svx[p] = vr;
        const float4* src = (q < 2)
            ? (const float4*)(g_voxf + (size_t)vr * 128 + q * 64)
            : (const float4*)(g_pf2 + (size_t)cp * 128 + (q - 2) * 64);
        float4* dst = (float4*)(sA + p * SA_ST + q * 64);
#pragma unroll
        for (int j = 0; j < 16; j++) {
            float4 v = src[j];
            v.x = tf32f(v.x); v.y = tf32f(v.y);
            v.z = tf32f(v.z); v.w = tf32f(v.w);
            dst[j] = v;
        }
    }

    float acc[2][8][4];
#pragma unroll
    for (int mt = 0; mt < 2; mt++)
#pragma unroll
        for (int nt = 0; nt < 8; nt++)
#pragma unroll
            for (int j = 0; j < 4; j++) acc[mt][nt][j] = 0.f;

    CP_WAIT0();
    __syncthreads();

    const float* wimg = (const float*)g_w3t;

#pragma unroll 1
    for (int gg = 0; gg < 2; gg++) {
#pragma unroll 1
        for (int kc = 0; kc < 8; kc++) {
            if (kc < 7) {
                ldB_async(wimg + (kc + 1) * 8192, bufu[(kc + 1) & 1], t);
                CP_COMMIT();
            } else if (gg == 0) {
                ldB_async((const float*)g_w4t, bufu[0], t);  // prefetch w4 chunk0
                CP_COMMIT();
            }
            mma_chunk(sA, sB + (kc & 1) * 32 * SB_ST, kc, wm, wn, g, t4, acc);
            CP_WAIT0();
            __syncthreads();
        }

        if (gg == 0) {
            // epilogue1: h = relu(acc + b3) -> sA (tf32), reset acc
#pragma unroll
            for (int nt = 0; nt < 8; nt++) {
                int c = wn * 64 + nt * 8 + 2 * t4;
                float bc0 = __ldg(b3 + c), bc1 = __ldg(b3 + c + 1);
#pragma unroll
                for (int mt = 0; mt < 2; mt++) {
                    int r = wm * 32 + mt * 16 + g;
                    float h0 = fmaxf(acc[mt][nt][0] + bc0, 0.f);
                    float h1 = fmaxf(acc[mt][nt][1] + bc1, 0.f);
                    float h2 = fmaxf(acc[mt][nt][2] + bc0, 0.f);
                    float h3 = fmaxf(acc[mt][nt][3] + bc1, 0.f);
                    *(float2*)(sA + r * SA_ST + c) = make_float2(tf32f(h0), tf32f(h1));
                    *(float2*)(sA + (r + 8) * SA_ST + c) = make_float2(tf32f(h2), tf32f(h3));
                    acc[mt][nt][0] = 0.f; acc[mt][nt][1] = 0.f;
                    acc[mt][nt][2] = 0.f; acc[mt][nt][3] = 0.f;
                }
            }
            wimg = (const float*)g_w4t;
            __syncthreads();
        }
    }

    // epilogue2: pf5 = relu(acc + b4) -> atomicMax scatter into g_vox2
#pragma unroll
    for (int mt = 0; mt < 2; mt++) {
        int lr = wm * 32 + mt * 16 + g;
        int pt0 = row0 + lr, pt1 = pt0 + 8;
        int vr0 = svx[lr], vr1 = svx[lr + 8];
        bool ok0 = pt0 < n, ok1 = pt1 < n;
        float* d0 = g_vox2 + (size_t)vr0 * 256;
        float* d1 = g_vox2 + (size_t)vr1 * 256;
#pragma unroll
        for (int nt = 0; nt < 8; nt++) {
            int c = wn * 64 + nt * 8 + 2 * t4;
            float bc0 = __ldg(b4 + c), bc1 = __ldg(b4 + c + 1);
            if (ok0) {
                amax_pos(d0 + c,     acc[mt][nt][0] + bc0);
                amax_pos(d0 + c + 1, acc[mt][nt][1] + bc1);
            }
            if (ok1) {
                amax_pos(d1 + c,     acc[mt][nt][2] + bc0);
                amax_pos(d1 + c + 1, acc[mt][nt][3] + bc1);
            }
        }
    }
}

// ---------------------------------------------------------------------------
// Output GEMM via mma + cp.async pipeline: out[M,256]=relu(A@Wt+bias), store.
// ---------------------------------------------------------------------------
__global__ __launch_bounds__(512) void gemm_out_mma(
    const float* __restrict__ A, const float* __restrict__ bias,
    float* __restrict__ out, int M)
{
    extern __shared__ float sm[];
    float* sA = sm;
    float* sB = sm + 128 * SA_ST;
    uint32_t sBu = smem_u32(sB);

    int t = threadIdx.x;
    int lane = t & 31, wid = t >> 5;
    int g = lane >> 2, t4 = lane & 3;
    int wm = wid & 3, wn = wid >> 2;
    int row0 = blockIdx.x * 128;
    const uint32_t bufu[2] = {sBu, sBu + 32u * SB_ST * 4u};

    ldB_async((const float*)g_wvt, bufu[0], t);
    CP_COMMIT();

    {
        int p = t >> 2, q = t & 3;
        int cp = min(row0 + p, M - 1);
        const float4* src = (const float4*)(A + (size_t)cp * 256 + q * 64);
        float4* dst = (float4*)(sA + p * SA_ST + q * 64);
#pragma unroll
        for (int j = 0; j < 16; j++) {
            float4 v = src[j];
            v.x = tf32f(v.x); v.y = tf32f(v.y);
            v.z = tf32f(v.z); v.w = tf32f(v.w);
            dst[j] = v;
        }
    }

    float acc[2][8][4];
#pragma unroll
    for (int mt = 0; mt < 2; mt++)
#pragma unroll
        for (int nt = 0; nt < 8; nt++)
#pragma unroll
            for (int j = 0; j < 4; j++) acc[mt][nt][j] = 0.f;

    CP_WAIT0();
    __syncthreads();

    const float* wimg = (const float*)g_wvt;
#pragma unroll 1
    for (int kc = 0; kc < 8; kc++) {
        if (kc < 7) {
            ldB_async(wimg + (kc + 1) * 8192, bufu[(kc + 1) & 1], t);
            CP_COMMIT();
        }
        mma_chunk(sA, sB + (kc & 1) * 32 * SB_ST, kc, wm, wn, g, t4, acc);
        CP_WAIT0();
        __syncthreads();
    }

#pragma unroll
    for (int mt = 0; mt < 2; mt++) {
        int lr = wm * 32 + mt * 16 + g;
        int r0 = row0 + lr, r1 = r0 + 8;
#pragma unroll
        for (int nt = 0; nt < 8; nt++) {
            int c = wn * 64 + nt * 8 + 2 * t4;
            float bc0 = __ldg(bias + c), bc1 = __ldg(bias + c + 1);
            if (r0 < M)
                *(float2*)(out + (size_t)r0 * 256 + c) =
                    make_float2(fmaxf(acc[mt][nt][0] + bc0, 0.f), fmaxf(acc[mt][nt][1] + bc1, 0.f));
            if (r1 < M)
                *(float2*)(out + (size_t)r1 * 256 + c) =
                    make_float2(fmaxf(acc[mt][nt][2] + bc0, 0.f), fmaxf(acc[mt][nt][3] + bc1, 0.f));
        }
    }
}

// ---------------------------------------------------------------------------
extern "C" void kernel_launch(void* const* d_in, const int* in_sizes, int n_in,
                              void* d_out, int out_size)
{
    const float* inp  = (const float*)d_in[0];
    const int*   vidx = (const int*)d_in[1];
    int base = (n_in >= 23) ? 3 : 2;
    const float* w1x = (const float*)d_in[base + 0];
    const float* b1x = (const float*)d_in[base + 1];
    const float* w2x = (const float*)d_in[base + 2];
    const float* b2x = (const float*)d_in[base + 3];
    const float* w1r = (const float*)d_in[base + 4];
    const float* b1r = (const float*)d_in[base + 5];
    const float* w2r = (const float*)d_in[base + 6];
    const float* b2r = (const float*)d_in[base + 7];
    const float* wax = (const float*)d_in[base + 8];
    const float* bax = (const float*)d_in[base + 9];
    const float* war = (const float*)d_in[base + 10];
    const float* bar = (const float*)d_in[base + 11];
    const float* wv1 = (const float*)d_in[base + 12];
    const float* bv1 = (const float*)d_in[base + 13];
    const float* w3  = (const float*)d_in[base + 14];
    const float* b3  = (const float*)d_in[base + 15];
    const float* w4  = (const float*)d_in[base + 16];
    const float* b4  = (const float*)d_in[base + 17];
    const float* wv2 = (const float*)d_in[base + 18];
    const float* bv2 = (const float*)d_in[base + 19];

    int n = in_sizes[0] / 6;
    int V = out_size / 256;

    const int G1_SMEM = (128 * 68 + 32 * 128) * 4;

    cudaFuncSetAttribute(stage_a_mma, cudaFuncAttributeMaxDynamicSharedMemorySize, SAM_SMEM);
    cudaFuncSetAttribute(stage_c_mma, cudaFuncAttributeMaxDynamicSharedMemorySize, SC_SMEM);
    cudaFuncSetAttribute(gemm_out_mma, cudaFuncAttributeMaxDynamicSharedMemorySize, SC_SMEM);
    cudaFuncSetAttribute(gemm_relu<128, 128>, cudaFuncAttributeMaxDynamicSharedMemorySize, G1_SMEM);

    float *p_vox, *p_voxf, *p_vox2, *p_w3t, *p_w4t, *p_wvt;
    cudaGetSymbolAddress((void**)&p_vox, g_vox);
    cudaGetSymbolAddress((void**)&p_voxf, g_voxf);
    cudaGetSymbolAddress((void**)&p_vox2, g_vox2);
    cudaGetSymbolAddress((void**)&p_w3t, g_w3t);
    cudaGetSymbolAddress((void**)&p_w4t, g_w4t);
    cudaGetSymbolAddress((void**)&p_wvt, g_wvt);

    int zb = (V * 256 + 255) / 256;
    zero_k<<<zb, 256>>>(V * 128, V * 256);
    prep_tf32<<<256, 256>>>(w3, p_w3t);
    prep_tf32<<<256, 256>>>(w4, p_w4t);
    prep_tf32<<<256, 256>>>(wv2, p_wvt);

    stage_a_mma<<<(n + 127) / 128, SAM_THREADS, SAM_SMEM>>>(
        inp, vidx, n, w1x, b1x, w2x, b2x, w1r, b1r, w2r, b2r, wax, bax, war, bar);

    gemm_relu<128, 128><<<(V + 63) / 64, 256, G1_SMEM>>>(p_vox, wv1, bv1, p_voxf, V);

    stage_c_mma<<<(n + 127) / 128, 512, SC_SMEM>>>(vidx, n, b3, b4);

    gemm_out_mma<<<(V + 127) / 128, 512, SC_SMEM>>>(p_vox2, bv2, (float*)d_out, V);
}

// round 7
// speedup vs baseline: 1.6203x; 1.6203x over previous
#include <cuda_runtime.h>
#include <cuda_bf16.h>
#include <cstdint>
#include <math.h>

#define MAXN 500000
#define MAXV 50000

// ---- scratch (static __device__ arrays; allocation-free) ----
__device__ __align__(128) float g_pf2[(size_t)MAXN * 128];
__device__ __align__(128) float g_vox[(size_t)MAXV * 128];
__device__ __align__(128) float g_voxf[(size_t)MAXV * 128];
__device__ __align__(128) float g_vox2[(size_t)MAXV * 256];
__device__ __align__(128) __nv_bfloat16 g_w3b[81920];  // w3 blocked bf16 [8 kc][256 n][40 k]
__device__ __align__(128) __nv_bfloat16 g_w4b[81920];  // w4 blocked bf16
__device__ __align__(128) float g_wvt[65536];           // wv2 tf32

__device__ __forceinline__ void amax_pos(float* addr, float v) {
    if (v > 0.f) atomicMax((int*)addr, __float_as_int(v));
}

__device__ __forceinline__ uint32_t f2tf32(float f) {
    uint32_t r;
    asm("cvt.rna.tf32.f32 %0, %1;" : "=r"(r) : "f"(f));
    return r;
}
__device__ __forceinline__ float tf32f(float f) { return __uint_as_float(f2tf32(f)); }

__device__ __forceinline__ uint32_t pack_bf16(float a, float b) {
    __nv_bfloat162 h = __floats2bfloat162_rn(a, b);   // .x = a (low), .y = b (high)
    uint32_t r;
    memcpy(&r, &h, 4);
    return r;
}

__device__ __forceinline__ uint32_t smem_u32(const void* p) {
    return (uint32_t)__cvta_generic_to_shared(p);
}
__device__ __forceinline__ void cp_async16(uint32_t dst, const void* src) {
    asm volatile("cp.async.cg.shared.global [%0], [%1], 16;" :: "r"(dst), "l"(src));
}
#define CP_COMMIT() asm volatile("cp.async.commit_group;" ::: "memory")
#define CP_WAIT0()  asm volatile("cp.async.wait_group 0;" ::: "memory")

// ---------------------------------------------------------------------------
__global__ void zero_k(int na, int nb) {
    int i = blockIdx.x * blockDim.x + threadIdx.x;
    int stride = gridDim.x * blockDim.x;
    for (int j = i; j < nb; j += stride) {
        if (j < na) g_vox[j] = 0.f;
        g_vox2[j] = 0.f;
    }
}

__global__ void prep_tf32(const float* __restrict__ w, float* __restrict__ dst) {
    int i = blockIdx.x * blockDim.x + threadIdx.x;
    if (i < 65536) dst[i] = __uint_as_float(f2tf32(w[i]));
}

// w [k=256][n=256] row-major -> blocked bf16 image [kc][n][40] (pad 8 zeros)
__global__ void prep_wb(const float* __restrict__ w, __nv_bfloat16* __restrict__ dst) {
    int i = blockIdx.x * blockDim.x + threadIdx.x;
    if (i >= 81920) return;
    int kc = i / 10240, rem = i % 10240, nn = rem / 40, kl = rem % 40;
    float v = (kl < 32) ? w[(size_t)(kc * 32 + kl) * 256 + nn] : 0.f;
    dst[i] = __float2bfloat16(v);
}

// ---------------------------------------------------------------------------
// warp micro-GEMM helper: [16x64]@[64x32] tf32, A stride 68, B stride 40
// ---------------------------------------------------------------------------
__device__ __forceinline__ void gemm64x32(const float* __restrict__ As,
                                          const float* __restrict__ Bt,
                                          int wr, int g, int t4, float acc[4][4]) {
#pragma unroll
    for (int k8 = 0; k8 < 8; k8++) {
        const float* ap = As + (wr + g) * 68 + k8 * 8 + t4;
        uint32_t a0 = __float_as_uint(ap[0]);
        uint32_t a1 = __float_as_uint(ap[8 * 68]);
        uint32_t a2 = __float_as_uint(ap[4]);
        uint32_t a3 = __float_as_uint(ap[8 * 68 + 4]);
#pragma unroll
        for (int nt = 0; nt < 4; nt++) {
            const float* bp = Bt + (k8 * 8 + t4) * 40 + nt * 8 + g;
            uint32_t b0 = __float_as_uint(bp[0]);
            uint32_t b1 = __float_as_uint(bp[4 * 40]);
            asm volatile(
                "mma.sync.aligned.m16n8k8.row.col.f32.tf32.tf32.f32 "
                "{%0,%1,%2,%3},{%4,%5,%6,%7},{%8,%9},{%0,%1,%2,%3};"
                : "+f"(acc[nt][0]), "+f"(acc[nt][1]), "+f"(acc[nt][2]), "+f"(acc[nt][3])
                : "r"(a0), "r"(a1), "r"(a2), "r"(a3), "r"(b0), "r"(b1));
        }
    }
}

// ---------------------------------------------------------------------------
// Stage A via mma.sync tf32 (unchanged from R5)
// ---------------------------------------------------------------------------
#define SAM_THREADS 256
#define SAM_SMEM (28288 * 4)

__global__ __launch_bounds__(SAM_THREADS) void stage_a_mma(
    const float* __restrict__ inp, const int* __restrict__ vidx, int n,
    const float* __restrict__ w1x, const float* __restrict__ b1x,
    const float* __restrict__ w2x, const float* __restrict__ b2x,
    const float* __restrict__ w1r, const float* __restrict__ b1r,
    const float* __restrict__ w2r, const float* __restrict__ b2r,
    const float* __restrict__ wax, const float* __restrict__ bax,
    const float* __restrict__ war, const float* __restrict__ bar)
{
    extern __shared__ float sm[];
    float* sW = sm;
    float* sB = sm + 512;
    float* sA = sm + 10752;
    float* sC = sm + 19456;
    int*   svx = (int*)(sm + 28160);

    int t = threadIdx.x;
    int lane = t & 31, w = t >> 5;
    int g = lane >> 2, t4 = lane & 3;
    int wr = 16 * w;
    int row0 = blockIdx.x * 128;

    for (int i = t; i < 192; i += SAM_THREADS) { sW[i] = w1x[i]; sW[256 + i] = w1r[i]; }
    for (int i = t; i < 64; i += SAM_THREADS)  { sW[192 + i] = b1x[i]; sW[448 + i] = b1r[i]; }
    {
        const float* wsrc[4] = {w2x, w2r, wax, war};
#pragma unroll
        for (int a = 0; a < 4; a++) {
            float* dst = sB + a * 2560;
            const float* s = wsrc[a];
            for (int i = t; i < 2048; i += SAM_THREADS) {
                int k = i >> 5, c = i & 31;
                dst[k * 40 + c] = __uint_as_float(f2tf32(s[i]));
            }
        }
    }
    __syncthreads();

    int p = t >> 1, half = t & 1;
    int cp = min(row0 + p, n - 1);
    if (half == 0) svx[p] = vidx[cp];
    float i0 = inp[(size_t)cp * 6 + 0], i1 = inp[(size_t)cp * 6 + 1], i2 = inp[(size_t)cp * 6 + 2];
    float i3 = inp[(size_t)cp * 6 + 3], i4 = inp[(size_t)cp * 6 + 4], i5 = inp[(size_t)cp * 6 + 5];

    {
        const float* W = sW; const float* B = sW + 192;
        int ob = half * 32;
#pragma unroll 8
        for (int o = 0; o < 32; o++) {
            int oo = ob + o;
            float a = B[oo] + i0 * W[oo] + i1 * W[64 + oo] + i2 * W[128 + oo];
            sA[p * 68 + oo] = tf32f(fmaxf(a, 0.f));
        }
    }
    __syncwarp();

    float fx[4][4];
#pragma unroll
    for (int nt = 0; nt < 4; nt++)
#pragma unroll
        for (int j = 0; j < 4; j++) fx[nt][j] = 0.f;
    gemm64x32(sA, sB, wr, g, t4, fx);
    __syncwarp();

#pragma unroll
    for (int nt = 0; nt < 4; nt++) {
        int c = nt * 8 + 2 * t4;
        float bc0 = __ldg(b2x + c), bc1 = __ldg(b2x + c + 1);
        fx[nt][0] = fmaxf(fx[nt][0] + bc0, 0.f);
        fx[nt][1] = fmaxf(fx[nt][1] + bc1, 0.f);
        fx[nt][2] = fmaxf(fx[nt][2] + bc0, 0.f);
        fx[nt][3] = fmaxf(fx[nt][3] + bc1, 0.f);
        int r = wr + g;
        *(float2*)(sC + r * 68 + c) = make_float2(tf32f(fx[nt][0]), tf32f(fx[nt][1]));
        *(float2*)(sC + (r + 8) * 68 + c) = make_float2(tf32f(fx[nt][2]), tf32f(fx[nt][3]));
    }
    {
        const float* W = sW + 256; const float* B = sW + 448;
        int ob = half * 32;
#pragma unroll 8
        for (int o = 0; o < 32; o++) {
            int oo = ob + o;
            float a = B[oo] + i3 * W[oo] + i4 * W[64 + oo] + i5 * W[128 + oo];
            sA[p * 68 + oo] = tf32f(fmaxf(a, 0.f));
        }
    }
    __syncwarp();

    float fr[4][4];
#pragma unroll
    for (int nt = 0; nt < 4; nt++)
#pragma unroll
        for (int j = 0; j < 4; j++) fr[nt][j] = 0.f;
    gemm64x32(sA, sB + 2560, wr, g, t4, fr);
#pragma unroll
    for (int nt = 0; nt < 4; nt++) {
        int c = nt * 8 + 2 * t4;
        float bc0 = __ldg(b2r + c), bc1 = __ldg(b2r + c + 1);
        fr[nt][0] = fmaxf(fr[nt][0] + bc0, 0.f);
        fr[nt][1] = fmaxf(fr[nt][1] + bc1, 0.f);
        fr[nt][2] = fmaxf(fr[nt][2] + bc0, 0.f);
        fr[nt][3] = fmaxf(fr[nt][3] + bc1, 0.f);
        int r = wr + g;
        *(float2*)(sC + r * 68 + 32 + c) = make_float2(tf32f(fr[nt][0]), tf32f(fr[nt][1]));
        *(float2*)(sC + (r + 8) * 68 + 32 + c) = make_float2(tf32f(fr[nt][2]), tf32f(fr[nt][3]));
    }
    __syncwarp();

    float ax[4][4], ar[4][4];
#pragma unroll
    for (int nt = 0; nt < 4; nt++)
#pragma unroll
        for (int j = 0; j < 4; j++) { ax[nt][j] = 0.f; ar[nt][j] = 0.f; }
    gemm64x32(sC, sB + 2 * 2560, wr, g, t4, ax);
    gemm64x32(sC, sB + 3 * 2560, wr, g, t4, ar);

#pragma unroll
    for (int h2 = 0; h2 < 2; h2++) {
        int r = wr + g + 8 * h2;
        int pt = row0 + r;
        if (pt < n) {
            int vr = svx[r];
            float* pfr = g_pf2 + (size_t)pt * 128;
            float* vxr = g_vox + (size_t)vr * 128;
#pragma unroll
            for (int nt = 0; nt < 4; nt++) {
                int c = nt * 8 + 2 * t4;
                int j0 = 2 * h2, j1 = 2 * h2 + 1;
                float axa = ax[nt][j0] + __ldg(bax + c);
                float axb = ax[nt][j1] + __ldg(bax + c + 1);
                float ara = ar[nt][j0] + __ldg(bar + c);
                float arb = ar[nt][j1] + __ldg(bar + c + 1);
                float sxa = 1.f / (1.f + __expf(-axa));
                float sxb = 1.f / (1.f + __expf(-axb));
                float sra = 1.f / (1.f + __expf(-ara));
                float srb = 1.f / (1.f + __expf(-arb));
                float fxa = fx[nt][j0], fxb = fx[nt][j1];
                float fra = fr[nt][j0], frb = fr[nt][j1];
                float v1a = fxa * sxa, v1b = fxb * sxb;
                float v3a = fra * sra, v3b = frb * srb;
                *(float2*)(pfr + c)      = make_float2(fxa, fxb);
                *(float2*)(pfr + 32 + c) = make_float2(v1a, v1b);
                *(float2*)(pfr + 64 + c) = make_float2(fra, frb);
                *(float2*)(pfr + 96 + c) = make_float2(v3a, v3b);
                amax_pos(vxr + c, fxa);        amax_pos(vxr + c + 1, fxb);
                amax_pos(vxr + 32 + c, v1a);   amax_pos(vxr + 33 + c, v1b);
                amax_pos(vxr + 64 + c, fra);   amax_pos(vxr + 65 + c, frb);
                amax_pos(vxr + 96 + c, v3a);   amax_pos(vxr + 97 + c, v3b);
            }
        }
    }
}

// ---------------------------------------------------------------------------
// Generic tiled fp32 GEMM (kept for the small wv1 layer)
// ---------------------------------------------------------------------------
template <int K, int NC>
__global__ __launch_bounds__(256) void gemm_relu(
    const float* __restrict__ A, const float* __restrict__ W,
    const float* __restrict__ bias, float* __restrict__ out, int M)
{
    extern __shared__ float sm[];
    float* a_s = sm;
    float* b_s = sm + K * 68;
    const int TN = NC / 32;
    int t = threadIdx.x;
    int c = t & 31, r = t >> 5;
    int row0 = blockIdx.x * 64;
    {
        int row = t >> 2, q = t & 3;
        int gr = min(row0 + row, M - 1);
        const float4* src = (const float4*)(A + (size_t)gr * K + q * (K / 4));
#pragma unroll
        for (int u = 0; u < K / 16; ++u) {
            float4 v = src[u];
            int k = q * (K / 4) + 4 * u;
            a_s[(k + 0) * 68 + row] = v.x;
            a_s[(k + 1) * 68 + row] = v.y;
            a_s[(k + 2) * 68 + row] = v.z;
            a_s[(k + 3) * 68 + row] = v.w;
        }
    }
    float acc[8][TN];
#pragma unroll
    for (int i = 0; i < 8; i++)
#pragma unroll
        for (int j = 0; j < TN; j++) acc[i][j] = 0.f;
    for (int kc = 0; kc < K / 32; ++kc) {
        {
            const float4* ws = (const float4*)(W + (size_t)(kc * 32 + (t >> 3)) * NC + (t & 7) * (NC / 8));
            float4* wd = (float4*)(b_s + (t >> 3) * NC + (t & 7) * (NC / 8));
#pragma unroll
            for (int q = 0; q < NC / 32; q++) wd[q] = ws[q];
        }
        __syncthreads();
#pragma unroll
        for (int k = 0; k < 32; k++) {
            const float* ar = a_s + (kc * 32 + k) * 68 + 8 * r;
            float4 a0 = *(const float4*)ar;
            float4 a1 = *(const float4*)(ar + 4);
            float av[8] = {a0.x, a0.y, a0.z, a0.w, a1.x, a1.y, a1.z, a1.w};
            const float* br = b_s + k * NC + 4 * c;
            float bv[TN];
            {
                float4 b0 = *(const float4*)br;
                bv[0] = b0.x; bv[1] = b0.y; bv[2] = b0.z; bv[3] = b0.w;
            }
            if (TN == 8) {
                float4 b1v = *(const float4*)(br + NC / 2);
                bv[4] = b1v.x; bv[5] = b1v.y; bv[6] = b1v.z; bv[7] = b1v.w;
            }
#pragma unroll
            for (int i = 0; i < 8; i++)
#pragma unroll
                for (int j = 0; j < TN; j++) acc[i][j] += av[i] * bv[j];
        }
        __syncthreads();
    }
    float bb[TN];
#pragma unroll
    for (int j = 0; j < TN; j++) {
        int col = (j < 4) ? 4 * c + j : NC / 2 + 4 * c + (j - 4);
        bb[j] = bias[col];
    }
#pragma unroll
    for (int i = 0; i < 8; i++) {
        int row = row0 + 8 * r + i;
        if (row < M) {
#pragma unroll
            for (int j = 0; j < TN; j++) {
                int col = (j < 4) ? 4 * c + j : NC / 2 + 4 * c + (j - 4);
                out[(size_t)row * NC + col] = fmaxf(acc[i][j] + bb[j], 0.f);
            }
        }
    }
}

// ---------------------------------------------------------------------------
// Stage C v4 (bf16): 64-point tiles, 256 threads, 2 CTAs/SM.
//   8 warps (2m x 4n), warp tile 32x64, mma m16n8k16 bf16, fp32 accum.
//   A bf16 in smem stride 264 (u32 stride 132); B blocked [n=256][40] bf16.
//   cp.async double-buffered weight stream (chunks of k=32).
// ---------------------------------------------------------------------------
#define SC4_A_U32   (64 * 132)            // 8448 u32 = 33792 B
#define SC4_B_U32   (2 * 5120)            // 2 chunks x 256*20 u32 = 40960 B
#define SC4_SMEM    ((SC4_A_U32 + SC4_B_U32 + 64) * 4)

// async-load one blocked bf16 weight chunk (1280 float4) into sB buffer
__device__ __forceinline__ void ldBb_async(const __nv_bfloat16* __restrict__ ws,
                                           uint32_t dstu, int t) {
#pragma unroll
    for (int i = 0; i < 5; i++) {
        int e = t + i * 256;
        cp_async16(dstu + (uint32_t)e * 16u, (const float4*)ws + e);
    }
}

__device__ __forceinline__ void mma_chunk_bf16(const uint32_t* __restrict__ sA32,
                                               const uint32_t* __restrict__ B32,
                                               int kc, int wm, int wn, int g, int t4,
                                               float acc[2][8][4]) {
#pragma unroll
    for (int s = 0; s < 2; s++) {
        int kw = kc * 16 + s * 8 + t4;      // u32 word index within A row (132/row)
        uint32_t a[2][4];
#pragma unroll
        for (int mt = 0; mt < 2; mt++) {
            const uint32_t* ap = sA32 + (wm * 32 + mt * 16 + g) * 132 + kw;
            a[mt][0] = ap[0];
            a[mt][1] = ap[8 * 132];
            a[mt][2] = ap[4];
            a[mt][3] = ap[8 * 132 + 4];
        }
        int bw = s * 8 + t4;                // u32 word within B row (20/row)
#pragma unroll
        for (int nt = 0; nt < 8; nt++) {
            const uint32_t* bp = B32 + (wn * 64 + nt * 8 + g) * 20 + bw;
            uint32_t b0 = bp[0], b1 = bp[4];
#pragma unroll
            for (int mt = 0; mt < 2; mt++) {
                asm volatile(
                    "mma.sync.aligned.m16n8k16.row.col.f32.bf16.bf16.f32 "
                    "{%0,%1,%2,%3},{%4,%5,%6,%7},{%8,%9},{%0,%1,%2,%3};"
                    : "+f"(acc[mt][nt][0]), "+f"(acc[mt][nt][1]),
                      "+f"(acc[mt][nt][2]), "+f"(acc[mt][nt][3])
                    : "r"(a[mt][0]), "r"(a[mt][1]), "r"(a[mt][2]), "r"(a[mt][3]),
                      "r"(b0), "r"(b1));
            }
        }
    }
}

__global__ __launch_bounds__(256, 2) void stage_c_bf16(
    const int* __restrict__ vidx, int n,
    const float* __restrict__ b3, const float* __restrict__ b4)
{
    extern __shared__ uint32_t su[];
    uint32_t* sA32 = su;                    // [64][132] bf16x2
    uint32_t* sB32 = su + SC4_A_U32;        // [2][256*20]
    int* svx = (int*)(su + SC4_A_U32 + SC4_B_U32);
    uint32_t sBu = smem_u32(sB32);
    const uint32_t bufu[2] = {sBu, sBu + 5120u * 4u};

    int t = threadIdx.x;
    int lane = t & 31, wid = t >> 5;
    int g = lane >> 2, t4 = lane & 3;
    int wm = wid & 1, wn = wid >> 1;
    int row0 = blockIdx.x * 64;

    // prologue: start async load of w3 chunk 0 BEFORE the gather
    ldBb_async(g_w3b, bufu[0], t);
    CP_COMMIT();

    // ---- gather pf3 = [voxf[vidx[p]], pf2[p]] into sA as bf16 ----
    {
        int p = t >> 2, q = t & 3;
        int pt = row0 + p;
        int cp = min(pt, n - 1);
        int vr = vidx[cp];
        if (q == 0) svx[p] = vr;
        const float4* src = (q < 2)
            ? (const float4*)(g_voxf + (size_t)vr * 128 + q * 64)
            : (const float4*)(g_pf2 + (size_t)cp * 128 + (q - 2) * 64);
        uint32_t* dst = sA32 + p * 132 + q * 32;
#pragma unroll
        for (int j = 0; j < 16; j++) {
            float4 v = src[j];
            dst[2 * j]     = pack_bf16(v.x, v.y);
            dst[2 * j + 1] = pack_bf16(v.z, v.w);
        }
    }

    float acc[2][8][4];
#pragma unroll
    for (int mt = 0; mt < 2; mt++)
#pragma unroll
        for (int nt = 0; nt < 8; nt++)
#pragma unroll
            for (int j = 0; j < 4; j++) acc[mt][nt][j] = 0.f;

    CP_WAIT0();
    __syncthreads();

    const __nv_bfloat16* wimg = g_w3b;

#pragma unroll 1
    for (int gg = 0; gg < 2; gg++) {
#pragma unroll 1
        for (int kc = 0; kc < 8; kc++) {
            if (kc < 7) {
                ldBb_async(wimg + (kc + 1) * 10240, bufu[(kc + 1) & 1], t);
                CP_COMMIT();
            } else if (gg == 0) {
                ldBb_async(g_w4b, bufu[0], t);   // prefetch w4 chunk 0
                CP_COMMIT();
            }
            mma_chunk_bf16(sA32, sB32 + (kc & 1) * 5120, kc, wm, wn, g, t4, acc);
            CP_WAIT0();
            __syncthreads();
        }

        if (gg == 0) {
            // epilogue1: h = relu(acc + b3) -> sA (bf16), reset acc
#pragma unroll
            for (int nt = 0; nt < 8; nt++) {
                int c = wn * 64 + nt * 8 + 2 * t4;
                float bc0 = __ldg(b3 + c), bc1 = __ldg(b3 + c + 1);
#pragma unroll
                for (int mt = 0; mt < 2; mt++) {
                    int r = wm * 32 + mt * 16 + g;
                    float h0 = fmaxf(acc[mt][nt][0] + bc0, 0.f);
                    float h1 = fmaxf(acc[mt][nt][1] + bc1, 0.f);
                    float h2 = fmaxf(acc[mt][nt][2] + bc0, 0.f);
                    float h3 = fmaxf(acc[mt][nt][3] + bc1, 0.f);
                    sA32[r * 132 + (c >> 1)]       = pack_bf16(h0, h1);
                    sA32[(r + 8) * 132 + (c >> 1)] = pack_bf16(h2, h3);
                    acc[mt][nt][0] = 0.f; acc[mt][nt][1] = 0.f;
                    acc[mt][nt][2] = 0.f; acc[mt][nt][3] = 0.f;
                }
            }
            wimg = g_w4b;
            __syncthreads();
        }
    }

    // epilogue2: pf5 = relu(acc + b4) -> atomicMax scatter into g_vox2
#pragma unroll
    for (int mt = 0; mt < 2; mt++) {
        int lr = wm * 32 + mt * 16 + g;
        int pt0 = row0 + lr, pt1 = pt0 + 8;
        int vr0 = svx[lr], vr1 = svx[lr + 8];
        bool ok0 = pt0 < n, ok1 = pt1 < n;
        float* d0 = g_vox2 + (size_t)vr0 * 256;
        float* d1 = g_vox2 + (size_t)vr1 * 256;
#pragma unroll
        for (int nt = 0; nt < 8; nt++) {
            int c = wn * 64 + nt * 8 + 2 * t4;
            float bc0 = __ldg(b4 + c), bc1 = __ldg(b4 + c + 1);
            if (ok0) {
                amax_pos(d0 + c,     acc[mt][nt][0] + bc0);
                amax_pos(d0 + c + 1, acc[mt][nt][1] + bc1);
            }
            if (ok1) {
                amax_pos(d1 + c,     acc[mt][nt][2] + bc0);
                amax_pos(d1 + c + 1, acc[mt][nt][3] + bc1);
            }
        }
    }
}

// ---------------------------------------------------------------------------
// Output GEMM via mma tf32 (R5 reg-staged version, unchanged)
// ---------------------------------------------------------------------------
#define SA_ST 260
#define SB_ST 264
#define SC_SMEM ((128 * SA_ST + 2 * 32 * SB_ST + 128) * 4)

__global__ __launch_bounds__(512) void gemm_out_mma(
    const float* __restrict__ A, const float* __restrict__ bias,
    float* __restrict__ out, int M)
{
    extern __shared__ float sm[];
    float* sA = sm;
    float* sB = sm + 128 * SA_ST;

    int t = threadIdx.x;
    int lane = t & 31, wid = t >> 5;
    int g = lane >> 2, t4 = lane & 3;
    int wm = wid & 3, wn = wid >> 2;
    int row0 = blockIdx.x * 128;

    {
        int p = t >> 2, q = t & 3;
        int cp = min(row0 + p, M - 1);
        const float4* src = (const float4*)(A + (size_t)cp * 256 + q * 64);
        float4* dst = (float4*)(sA + p * SA_ST + q * 64);
#pragma unroll
        for (int j = 0; j < 16; j++) {
            float4 v = src[j];
            v.x = tf32f(v.x); v.y = tf32f(v.y);
            v.z = tf32f(v.z); v.w = tf32f(v.w);
            dst[j] = v;
        }
    }

    float acc[2][8][4];
#pragma unroll
    for (int mt = 0; mt < 2; mt++)
#pragma unroll
        for (int nt = 0; nt < 8; nt++)
#pragma unroll
            for (int j = 0; j < 4; j++) acc[mt][nt][j] = 0.f;

    const float* wimg = (const float*)g_wvt;
    float4 pld[4];
    {
        const float4* ws = (const float4*)wimg;
#pragma unroll
        for (int i = 0; i < 4; i++) pld[i] = ws[t + i * 512];
#pragma unroll
        for (int i = 0; i < 4; i++) {
            int e = t + i * 512;
            int k = e >> 6, n4 = e & 63;
            *(float4*)(sB + k * SB_ST + n4 * 4) = pld[i];
        }
    }
    __syncthreads();

#pragma unroll 1
    for (int kc = 0; kc < 8; kc++) {
        if (kc < 7) {
            const float4* ws = (const float4*)(wimg + (kc + 1) * 8192);
#pragma unroll
            for (int i = 0; i < 4; i++) pld[i] = ws[t + i * 512];
        }
        const float* bufB = sB + (kc & 1) * 32 * SB_ST;
#pragma unroll
        for (int k8 = 0; k8 < 4; k8++) {
            int k0 = kc * 32 + k8 * 8;
            uint32_t a[2][4];
#pragma unroll
            for (int mt = 0; mt < 2; mt++) {
                const float* ap = sA + (wm * 32 + mt * 16 + g) * SA_ST + k0 + t4;
                a[mt][0] = __float_as_uint(ap[0]);
                a[mt][1] = __float_as_uint(ap[8 * SA_ST]);
                a[mt][2] = __float_as_uint(ap[4]);
                a[mt][3] = __float_as_uint(ap[8 * SA_ST + 4]);
            }
#pragma unroll
            for (int nt = 0; nt < 8; nt++) {
                const float* bp = bufB + (k8 * 8 + t4) * SB_ST + wn * 64 + nt * 8 + g;
                uint32_t b0 = __float_as_uint(bp[0]);
                uint32_t b1 = __float_as_uint(bp[4 * SB_ST]);
#pragma unroll
                for (int mt = 0; mt < 2; mt++) {
                    asm volatile(
                        "mma.sync.aligned.m16n8k8.row.col.f32.tf32.tf32.f32 "
                        "{%0,%1,%2,%3},{%4,%5,%6,%7},{%8,%9},{%0,%1,%2,%3};"
                        : "+f"(acc[mt][nt][0]), "+f"(acc[mt][nt][1]),
                          "+f"(acc[mt][nt][2]), "+f"(acc[mt][nt][3])
                        : "r"(a[mt][0]), "r"(a[mt][1]), "r"(a[mt][2]), "r"(a[mt][3]),
                          "r"(b0), "r"(b1));
                }
            }
        }
        __syncthreads();
        if (kc < 7) {
            float* nb = sB + ((kc + 1) & 1) * 32 * SB_ST;
#pragma unroll
            for (int i = 0; i < 4; i++) {
                int e = t + i * 512;
                int k = e >> 6, n4 = e & 63;
                *(float4*)(nb + k * SB_ST + n4 * 4) = pld[i];
            }
            __syncthreads();
        }
    }

#pragma unroll
    for (int mt = 0; mt < 2; mt++) {
        int lr = wm * 32 + mt * 16 + g;
        int r0 = row0 + lr, r1 = r0 + 8;
#pragma unroll
        for (int nt = 0; nt < 8; nt++) {
            int c = wn * 64 + nt * 8 + 2 * t4;
            float bc0 = __ldg(bias + c), bc1 = __ldg(bias + c + 1);
            if (r0 < M)
                *(float2*)(out + (size_t)r0 * 256 + c) =
                    make_float2(fmaxf(acc[mt][nt][0] + bc0, 0.f), fmaxf(acc[mt][nt][1] + bc1, 0.f));
            if (r1 < M)
                *(float2*)(out + (size_t)r1 * 256 + c) =
                    make_float2(fmaxf(acc[mt][nt][2] + bc0, 0.f), fmaxf(acc[mt][nt][3] + bc1, 0.f));
        }
    }
}

// ---------------------------------------------------------------------------
extern "C" void kernel_launch(void* const* d_in, const int* in_sizes, int n_in,
                              void* d_out, int out_size)
{
    const float* inp  = (const float*)d_in[0];
    const int*   vidx = (const int*)d_in[1];
    int base = (n_in >= 23) ? 3 : 2;
    const float* w1x = (const float*)d_in[base + 0];
    const float* b1x = (const float*)d_in[base + 1];
    const float* w2x = (const float*)d_in[base + 2];
    const float* b2x = (const float*)d_in[base + 3];
    const float* w1r = (const float*)d_in[base + 4];
    const float* b1r = (const float*)d_in[base + 5];
    const float* w2r = (const float*)d_in[base + 6];
    const float* b2r = (const float*)d_in[base + 7];
    const float* wax = (const float*)d_in[base + 8];
    const float* bax = (const float*)d_in[base + 9];
    const float* war = (const float*)d_in[base + 10];
    const float* bar = (const float*)d_in[base + 11];
    const float* wv1 = (const float*)d_in[base + 12];
    const float* bv1 = (const float*)d_in[base + 13];
    const float* w3  = (const float*)d_in[base + 14];
    const float* b3  = (const float*)d_in[base + 15];
    const float* w4  = (const float*)d_in[base + 16];
    const float* b4  = (const float*)d_in[base + 17];
    const float* wv2 = (const float*)d_in[base + 18];
    const float* bv2 = (const float*)d_in[base + 19];

    int n = in_sizes[0] / 6;
    int V = out_size / 256;

    const int G1_SMEM = (128 * 68 + 32 * 128) * 4;

    cudaFuncSetAttribute(stage_a_mma, cudaFuncAttributeMaxDynamicSharedMemorySize, SAM_SMEM);
    cudaFuncSetAttribute(stage_c_bf16, cudaFuncAttributeMaxDynamicSharedMemorySize, SC4_SMEM);
    cudaFuncSetAttribute(gemm_out_mma, cudaFuncAttributeMaxDynamicSharedMemorySize, SC_SMEM);
    cudaFuncSetAttribute(gemm_relu<128, 128>, cudaFuncAttributeMaxDynamicSharedMemorySize, G1_SMEM);

    float *p_vox, *p_voxf, *p_vox2, *p_wvt;
    __nv_bfloat16 *p_w3b, *p_w4b;
    cudaGetSymbolAddress((void**)&p_vox, g_vox);
    cudaGetSymbolAddress((void**)&p_voxf, g_voxf);
    cudaGetSymbolAddress((void**)&p_vox2, g_vox2);
    cudaGetSymbolAddress((void**)&p_w3b, g_w3b);
    cudaGetSymbolAddress((void**)&p_w4b, g_w4b);
    cudaGetSymbolAddress((void**)&p_wvt, g_wvt);

    int zb = (V * 256 + 255) / 256;
    zero_k<<<zb, 256>>>(V * 128, V * 256);
    prep_wb<<<320, 256>>>(w3, p_w3b);
    prep_wb<<<320, 256>>>(w4, p_w4b);
    prep_tf32<<<256, 256>>>(wv2, p_wvt);

    stage_a_mma<<<(n + 127) / 128, SAM_THREADS, SAM_SMEM>>>(
        inp, vidx, n, w1x, b1x, w2x, b2x, w1r, b1r, w2r, b2r, wax, bax, war, bar);

    gemm_relu<128, 128><<<(V + 63) / 64, 256, G1_SMEM>>>(p_vox, wv1, bv1, p_voxf, V);

    stage_c_bf16<<<(n + 63) / 64, 256, SC4_SMEM>>>(vidx, n, b3, b4);

    gemm_out_mma<<<(V + 127) / 128, 512, SC_SMEM>>>(p_vox2, bv2, (float*)d_out, V);
}

// round 8
// speedup vs baseline: 1.7644x; 1.0890x over previous
#include <cuda_runtime.h>
#include <cuda_bf16.h>
#include <cstdint>
#include <math.h>

#define MAXN 500000
#define MAXV 50000

// ---- scratch (static __device__ arrays; allocation-free) ----
__device__ __align__(128) __nv_bfloat16 g_pf2b[(size_t)MAXN * 128];   // pf2 bf16
__device__ __align__(128) float g_vox[(size_t)MAXV * 128];
__device__ __align__(128) __nv_bfloat16 g_voxfb[(size_t)MAXV * 128];  // voxf bf16
__device__ __align__(128) float g_vox2[(size_t)MAXV * 256];
__device__ __align__(128) __nv_bfloat16 g_w3b[81920];  // w3 blocked bf16 [8 kc][256 n][40 k]
__device__ __align__(128) __nv_bfloat16 g_w4b[81920];  // w4 blocked bf16
__device__ __align__(128) float g_wvt[65536];           // wv2 tf32

__device__ __forceinline__ void amax_pos(float* addr, float v) {
    if (v > 0.f) atomicMax((int*)addr, __float_as_int(v));
}

__device__ __forceinline__ uint32_t f2tf32(float f) {
    uint32_t r;
    asm("cvt.rna.tf32.f32 %0, %1;" : "=r"(r) : "f"(f));
    return r;
}
__device__ __forceinline__ float tf32f(float f) { return __uint_as_float(f2tf32(f)); }

__device__ __forceinline__ uint32_t pack_bf16(float a, float b) {
    __nv_bfloat162 h = __floats2bfloat162_rn(a, b);
    uint32_t r;
    memcpy(&r, &h, 4);
    return r;
}

__device__ __forceinline__ uint32_t smem_u32(const void* p) {
    return (uint32_t)__cvta_generic_to_shared(p);
}
__device__ __forceinline__ void cp_async16(uint32_t dst, const void* src) {
    asm volatile("cp.async.cg.shared.global [%0], [%1], 16;" :: "r"(dst), "l"(src));
}
#define CP_COMMIT() asm volatile("cp.async.commit_group;" ::: "memory")
#define CP_WAIT0()  asm volatile("cp.async.wait_group 0;" ::: "memory")

__device__ __forceinline__ void ldsm4(uint32_t& r0, uint32_t& r1, uint32_t& r2,
                                      uint32_t& r3, uint32_t addr) {
    asm volatile("ldmatrix.sync.aligned.m8n8.x4.shared.b16 {%0,%1,%2,%3}, [%4];"
                 : "=r"(r0), "=r"(r1), "=r"(r2), "=r"(r3) : "r"(addr));
}

// ---------------------------------------------------------------------------
__global__ void zero_k(int na, int nb) {
    int i = blockIdx.x * blockDim.x + threadIdx.x;
    int stride = gridDim.x * blockDim.x;
    for (int j = i; j < nb; j += stride) {
        if (j < na) g_vox[j] = 0.f;
        g_vox2[j] = 0.f;
    }
}

__global__ void prep_tf32(const float* __restrict__ w, float* __restrict__ dst) {
    int i = blockIdx.x * blockDim.x + threadIdx.x;
    if (i < 65536) dst[i] = __uint_as_float(f2tf32(w[i]));
}

// w [k=256][n=256] row-major -> blocked bf16 image [kc][n][40] (pad 8 zeros)
__global__ void prep_wb(const float* __restrict__ w, __nv_bfloat16* __restrict__ dst) {
    int i = blockIdx.x * blockDim.x + threadIdx.x;
    if (i >= 81920) return;
    int kc = i / 10240, rem = i % 10240, nn = rem / 40, kl = rem % 40;
    float v = (kl < 32) ? w[(size_t)(kc * 32 + kl) * 256 + nn] : 0.f;
    dst[i] = __float2bfloat16(v);
}

// ---------------------------------------------------------------------------
// warp micro-GEMM helper: [16x64]@[64x32] tf32, A stride 68, B stride 40
// ---------------------------------------------------------------------------
__device__ __forceinline__ void gemm64x32(const float* __restrict__ As,
                                          const float* __restrict__ Bt,
                                          int wr, int g, int t4, float acc[4][4]) {
#pragma unroll
    for (int k8 = 0; k8 < 8; k8++) {
        const float* ap = As + (wr + g) * 68 + k8 * 8 + t4;
        uint32_t a0 = __float_as_uint(ap[0]);
        uint32_t a1 = __float_as_uint(ap[8 * 68]);
        uint32_t a2 = __float_as_uint(ap[4]);
        uint32_t a3 = __float_as_uint(ap[8 * 68 + 4]);
#pragma unroll
        for (int nt = 0; nt < 4; nt++) {
            const float* bp = Bt + (k8 * 8 + t4) * 40 + nt * 8 + g;
            uint32_t b0 = __float_as_uint(bp[0]);
            uint32_t b1 = __float_as_uint(bp[4 * 40]);
            asm volatile(
                "mma.sync.aligned.m16n8k8.row.col.f32.tf32.tf32.f32 "
                "{%0,%1,%2,%3},{%4,%5,%6,%7},{%8,%9},{%0,%1,%2,%3};"
                : "+f"(acc[nt][0]), "+f"(acc[nt][1]), "+f"(acc[nt][2]), "+f"(acc[nt][3])
                : "r"(a0), "r"(a1), "r"(a2), "r"(a3), "r"(b0), "r"(b1));
        }
    }
}

// ---------------------------------------------------------------------------
// Stage A via mma.sync tf32; pf2 stored as bf16 (same rounding stage_c used)
// ---------------------------------------------------------------------------
#define SAM_THREADS 256
#define SAM_SMEM (28288 * 4)

__global__ __launch_bounds__(SAM_THREADS) void stage_a_mma(
    const float* __restrict__ inp, const int* __restrict__ vidx, int n,
    const float* __restrict__ w1x, const float* __restrict__ b1x,
    const float* __restrict__ w2x, const float* __restrict__ b2x,
    const float* __restrict__ w1r, const float* __restrict__ b1r,
    const float* __restrict__ w2r, const float* __restrict__ b2r,
    const float* __restrict__ wax, const float* __restrict__ bax,
    const float* __restrict__ war, const float* __restrict__ bar)
{
    extern __shared__ float sm[];
    float* sW = sm;
    float* sB = sm + 512;
    float* sA = sm + 10752;
    float* sC = sm + 19456;
    int*   svx = (int*)(sm + 28160);

    int t = threadIdx.x;
    int lane = t & 31, w = t >> 5;
    int g = lane >> 2, t4 = lane & 3;
    int wr = 16 * w;
    int row0 = blockIdx.x * 128;

    for (int i = t; i < 192; i += SAM_THREADS) { sW[i] = w1x[i]; sW[256 + i] = w1r[i]; }
    for (int i = t; i < 64; i += SAM_THREADS)  { sW[192 + i] = b1x[i]; sW[448 + i] = b1r[i]; }
    {
        const float* wsrc[4] = {w2x, w2r, wax, war};
#pragma unroll
        for (int a = 0; a < 4; a++) {
            float* dst = sB + a * 2560;
            const float* s = wsrc[a];
            for (int i = t; i < 2048; i += SAM_THREADS) {
                int k = i >> 5, c = i & 31;
                dst[k * 40 + c] = __uint_as_float(f2tf32(s[i]));
            }
        }
    }
    __syncthreads();

    int p = t >> 1, half = t & 1;
    int cp = min(row0 + p, n - 1);
    if (half == 0) svx[p] = vidx[cp];
    float i0 = inp[(size_t)cp * 6 + 0], i1 = inp[(size_t)cp * 6 + 1], i2 = inp[(size_t)cp * 6 + 2];
    float i3 = inp[(size_t)cp * 6 + 3], i4 = inp[(size_t)cp * 6 + 4], i5 = inp[(size_t)cp * 6 + 5];

    {
        const float* W = sW; const float* B = sW + 192;
        int ob = half * 32;
#pragma unroll 8
        for (int o = 0; o < 32; o++) {
            int oo = ob + o;
            float a = B[oo] + i0 * W[oo] + i1 * W[64 + oo] + i2 * W[128 + oo];
            sA[p * 68 + oo] = tf32f(fmaxf(a, 0.f));
        }
    }
    __syncwarp();

    float fx[4][4];
#pragma unroll
    for (int nt = 0; nt < 4; nt++)
#pragma unroll
        for (int j = 0; j < 4; j++) fx[nt][j] = 0.f;
    gemm64x32(sA, sB, wr, g, t4, fx);
    __syncwarp();

#pragma unroll
    for (int nt = 0; nt < 4; nt++) {
        int c = nt * 8 + 2 * t4;
        float bc0 = __ldg(b2x + c), bc1 = __ldg(b2x + c + 1);
        fx[nt][0] = fmaxf(fx[nt][0] + bc0, 0.f);
        fx[nt][1] = fmaxf(fx[nt][1] + bc1, 0.f);
        fx[nt][2] = fmaxf(fx[nt][2] + bc0, 0.f);
        fx[nt][3] = fmaxf(fx[nt][3] + bc1, 0.f);
        int r = wr + g;
        *(float2*)(sC + r * 68 + c) = make_float2(tf32f(fx[nt][0]), tf32f(fx[nt][1]));
        *(float2*)(sC + (r + 8) * 68 + c) = make_float2(tf32f(fx[nt][2]), tf32f(fx[nt][3]));
    }
    {
        const float* W = sW + 256; const float* B = sW + 448;
        int ob = half * 32;
#pragma unroll 8
        for (int o = 0; o < 32; o++) {
            int oo = ob + o;
            float a = B[oo] + i3 * W[oo] + i4 * W[64 + oo] + i5 * W[128 + oo];
            sA[p * 68 + oo] = tf32f(fmaxf(a, 0.f));
        }
    }
    __syncwarp();

    float fr[4][4];
#pragma unroll
    for (int nt = 0; nt < 4; nt++)
#pragma unroll
        for (int j = 0; j < 4; j++) fr[nt][j] = 0.f;
    gemm64x32(sA, sB + 2560, wr, g, t4, fr);
#pragma unroll
    for (int nt = 0; nt < 4; nt++) {
        int c = nt * 8 + 2 * t4;
        float bc0 = __ldg(b2r + c), bc1 = __ldg(b2r + c + 1);
        fr[nt][0] = fmaxf(fr[nt][0] + bc0, 0.f);
        fr[nt][1] = fmaxf(fr[nt][1] + bc1, 0.f);
        fr[nt][2] = fmaxf(fr[nt][2] + bc0, 0.f);
        fr[nt][3] = fmaxf(fr[nt][3] + bc1, 0.f);
        int r = wr + g;
        *(float2*)(sC + r * 68 + 32 + c) = make_float2(tf32f(fr[nt][0]), tf32f(fr[nt][1]));
        *(float2*)(sC + (r + 8) * 68 + 32 + c) = make_float2(tf32f(fr[nt][2]), tf32f(fr[nt][3]));
    }
    __syncwarp();

    float ax[4][4], ar[4][4];
#pragma unroll
    for (int nt = 0; nt < 4; nt++)
#pragma unroll
        for (int j = 0; j < 4; j++) { ax[nt][j] = 0.f; ar[nt][j] = 0.f; }
    gemm64x32(sC, sB + 2 * 2560, wr, g, t4, ax);
    gemm64x32(sC, sB + 3 * 2560, wr, g, t4, ar);

#pragma unroll
    for (int h2 = 0; h2 < 2; h2++) {
        int r = wr + g + 8 * h2;
        int pt = row0 + r;
        if (pt < n) {
            int vr = svx[r];
            uint32_t* pfr = (uint32_t*)(g_pf2b + (size_t)pt * 128);
            float* vxr = g_vox + (size_t)vr * 128;
#pragma unroll
            for (int nt = 0; nt < 4; nt++) {
                int c = nt * 8 + 2 * t4;
                int j0 = 2 * h2, j1 = 2 * h2 + 1;
                float axa = ax[nt][j0] + __ldg(bax + c);
                float axb = ax[nt][j1] + __ldg(bax + c + 1);
                float ara = ar[nt][j0] + __ldg(bar + c);
                float arb = ar[nt][j1] + __ldg(bar + c + 1);
                float sxa = 1.f / (1.f + __expf(-axa));
                float sxb = 1.f / (1.f + __expf(-axb));
                float sra = 1.f / (1.f + __expf(-ara));
                float srb = 1.f / (1.f + __expf(-arb));
                float fxa = fx[nt][j0], fxb = fx[nt][j1];
                float fra = fr[nt][j0], frb = fr[nt][j1];
                float v1a = fxa * sxa, v1b = fxb * sxb;
                float v3a = fra * sra, v3b = frb * srb;
                int cw = c >> 1;
                pfr[cw]      = pack_bf16(fxa, fxb);
                pfr[16 + cw] = pack_bf16(v1a, v1b);
                pfr[32 + cw] = pack_bf16(fra, frb);
                pfr[48 + cw] = pack_bf16(v3a, v3b);
                amax_pos(vxr + c, fxa);        amax_pos(vxr + c + 1, fxb);
                amax_pos(vxr + 32 + c, v1a);   amax_pos(vxr + 33 + c, v1b);
                amax_pos(vxr + 64 + c, fra);   amax_pos(vxr + 65 + c, frb);
                amax_pos(vxr + 96 + c, v3a);   amax_pos(vxr + 97 + c, v3b);
            }
        }
    }
}

// ---------------------------------------------------------------------------
// Tiled fp32 GEMM for wv1: out[M,128] = relu(A@W+b) stored as bf16
// ---------------------------------------------------------------------------
__global__ __launch_bounds__(256) void gemm_relu_b16(
    const float* __restrict__ A, const float* __restrict__ W,
    const float* __restrict__ bias, __nv_bfloat16* __restrict__ out, int M)
{
    const int K = 128, NC = 128;
    extern __shared__ float sm[];
    float* a_s = sm;
    float* b_s = sm + K * 68;
    int t = threadIdx.x;
    int c = t & 31, r = t >> 5;
    int row0 = blockIdx.x * 64;
    {
        int row = t >> 2, q = t & 3;
        int gr = min(row0 + row, M - 1);
        const float4* src = (const float4*)(A + (size_t)gr * K + q * 32);
#pragma unroll
        for (int u = 0; u < 8; ++u) {
            float4 v = src[u];
            int k = q * 32 + 4 * u;
            a_s[(k + 0) * 68 + row] = v.x;
            a_s[(k + 1) * 68 + row] = v.y;
            a_s[(k + 2) * 68 + row] = v.z;
            a_s[(k + 3) * 68 + row] = v.w;
        }
    }
    float acc[8][4];
#pragma unroll
    for (int i = 0; i < 8; i++)
#pragma unroll
        for (int j = 0; j < 4; j++) acc[i][j] = 0.f;
    for (int kc = 0; kc < 4; ++kc) {
        {
            const float4* ws = (const float4*)(W + (size_t)(kc * 32 + (t >> 3)) * NC + (t & 7) * 16);
            float4* wd = (float4*)(b_s + (t >> 3) * NC + (t & 7) * 16);
#pragma unroll
            for (int q = 0; q < 4; q++) wd[q] = ws[q];
        }
        __syncthreads();
#pragma unroll
        for (int k = 0; k < 32; k++) {
            const float* ar = a_s + (kc * 32 + k) * 68 + 8 * r;
            float4 a0 = *(const float4*)ar;
            float4 a1 = *(const float4*)(ar + 4);
            float av[8] = {a0.x, a0.y, a0.z, a0.w, a1.x, a1.y, a1.z, a1.w};
            const float* br = b_s + k * NC + 4 * c;
            float4 b0 = *(const float4*)br;
            float bv[4] = {b0.x, b0.y, b0.z, b0.w};
#pragma unroll
            for (int i = 0; i < 8; i++)
#pragma unroll
                for (int j = 0; j < 4; j++) acc[i][j] += av[i] * bv[j];
        }
        __syncthreads();
    }
    float bb[4];
#pragma unroll
    for (int j = 0; j < 4; j++) bb[j] = bias[4 * c + j];
#pragma unroll
    for (int i = 0; i < 8; i++) {
        int row = row0 + 8 * r + i;
        if (row < M) {
            uint32_t* od = (uint32_t*)(out + (size_t)row * NC + 4 * c);
            od[0] = pack_bf16(fmaxf(acc[i][0] + bb[0], 0.f), fmaxf(acc[i][1] + bb[1], 0.f));
            od[1] = pack_bf16(fmaxf(acc[i][2] + bb[2], 0.f), fmaxf(acc[i][3] + bb[3], 0.f));
        }
    }
}

// ---------------------------------------------------------------------------
// Stage C v5 (bf16 + ldmatrix): 64-point tiles, 256 threads, 2 CTAs/SM.
// ---------------------------------------------------------------------------
#define SC4_A_U32   (64 * 132)
#define SC4_B_U32   (2 * 5120)
#define SC4_SMEM    ((SC4_A_U32 + SC4_B_U32 + 64) * 4)

__device__ __forceinline__ void ldBb_async(const __nv_bfloat16* __restrict__ ws,
                                           uint32_t dstu, int t) {
#pragma unroll
    for (int i = 0; i < 5; i++) {
        int e = t + i * 256;
        cp_async16(dstu + (uint32_t)e * 16u, (const float4*)ws + e);
    }
}

__global__ __launch_bounds__(256, 2) void stage_c_bf16(
    const int* __restrict__ vidx, int n,
    const float* __restrict__ b3, const float* __restrict__ b4)
{
    extern __shared__ uint32_t su[];
    uint32_t* sA32 = su;                    // [64][132] bf16x2
    uint32_t* sB32 = su + SC4_A_U32;        // [2][256*20]
    int* svx = (int*)(su + SC4_A_U32 + SC4_B_U32);
    uint32_t sAu = smem_u32(sA32);
    uint32_t sBu = smem_u32(sB32);
    const uint32_t bufu[2] = {sBu, sBu + 5120u * 4u};

    int t = threadIdx.x;
    int lane = t & 31, wid = t >> 5;
    int g = lane >> 2, t4 = lane & 3;
    int wm = wid & 1, wn = wid >> 1;
    int row0 = blockIdx.x * 64;

    // ldmatrix lane-address bases
    uint32_t aA[2];
#pragma unroll
    for (int mt = 0; mt < 2; mt++)
        aA[mt] = sAu + (uint32_t)(((wm * 32 + mt * 16 + (lane & 15)) * 132 + (lane >> 4) * 4) * 4);
    uint32_t bBrel[4];
    {
        int mat = lane >> 3;
        int nt_off = (mat >> 1) * 8, half = mat & 1;
#pragma unroll
        for (int nt2 = 0; nt2 < 4; nt2++) {
            int row = wn * 64 + nt2 * 16 + nt_off + (lane & 7);
            bBrel[nt2] = (uint32_t)((row * 20 + half * 4) * 4);
        }
    }

    // prologue: start async load of w3 chunk 0 BEFORE the gather
    ldBb_async(g_w3b, bufu[0], t);
    CP_COMMIT();

    // ---- gather pf3 = [voxfb[vidx[p]], pf2b[p]] into sA (already bf16) ----
    {
        int p = t >> 2, q = t & 3;
        int pt = row0 + p;
        int cp = min(pt, n - 1);
        int vr = vidx[cp];
        if (q == 0) svx[p] = vr;
        const uint4* src = (q < 2)
            ? (const uint4*)(g_voxfb + (size_t)vr * 128 + q * 64)
            : (const uint4*)(g_pf2b + (size_t)cp * 128 + (q - 2) * 64);
        uint4* dst = (uint4*)(sA32 + p * 132 + q * 32);
#pragma unroll
        for (int j = 0; j < 8; j++) dst[j] = src[j];
    }

    float acc[2][8][4];
#pragma unroll
    for (int mt = 0; mt < 2; mt++)
#pragma unroll
        for (int nt = 0; nt < 8; nt++)
#pragma unroll
            for (int j = 0; j < 4; j++) acc[mt][nt][j] = 0.f;

    CP_WAIT0();
    __syncthreads();

    const __nv_bfloat16* wimg = g_w3b;

#pragma unroll 1
    for (int gg = 0; gg < 2; gg++) {
#pragma unroll 1
        for (int kc = 0; kc < 8; kc++) {
            if (kc < 7) {
                ldBb_async(wimg + (kc + 1) * 10240, bufu[(kc + 1) & 1], t);
                CP_COMMIT();
            } else if (gg == 0) {
                ldBb_async(g_w4b, bufu[0], t);
                CP_COMMIT();
            }
            uint32_t bbase = bufu[kc & 1];
#pragma unroll
            for (int s = 0; s < 2; s++) {
                uint32_t a[2][4];
                ldsm4(a[0][0], a[0][1], a[0][2], a[0][3], aA[0] + (uint32_t)((kc * 16 + s * 8) * 4));
                ldsm4(a[1][0], a[1][1], a[1][2], a[1][3], aA[1] + (uint32_t)((kc * 16 + s * 8) * 4));
                uint32_t b[8][2];
#pragma unroll
                for (int nt2 = 0; nt2 < 4; nt2++)
                    ldsm4(b[2 * nt2][0], b[2 * nt2][1], b[2 * nt2 + 1][0], b[2 * nt2 + 1][1],
                          bbase + bBrel[nt2] + (uint32_t)(s * 32));
#pragma unroll
                for (int nt = 0; nt < 8; nt++)
#pragma unroll
                    for (int mt = 0; mt < 2; mt++) {
                        asm volatile(
                            "mma.sync.aligned.m16n8k16.row.col.f32.bf16.bf16.f32 "
                            "{%0,%1,%2,%3},{%4,%5,%6,%7},{%8,%9},{%0,%1,%2,%3};"
                            : "+f"(acc[mt][nt][0]), "+f"(acc[mt][nt][1]),
                              "+f"(acc[mt][nt][2]), "+f"(acc[mt][nt][3])
                            : "r"(a[mt][0]), "r"(a[mt][1]), "r"(a[mt][2]), "r"(a[mt][3]),
                              "r"(b[nt][0]), "r"(b[nt][1]));
                    }
            }
            CP_WAIT0();
            __syncthreads();
        }

        if (gg == 0) {
            // epilogue1: h = relu(acc + b3) -> sA (bf16), reset acc
#pragma unroll
            for (int nt = 0; nt < 8; nt++) {
                int c = wn * 64 + nt * 8 + 2 * t4;
                float bc0 = __ldg(b3 + c), bc1 = __ldg(b3 + c + 1);
#pragma unroll
                for (int mt = 0; mt < 2; mt++) {
                    int r = wm * 32 + mt * 16 + g;
                    float h0 = fmaxf(acc[mt][nt][0] + bc0, 0.f);
                    float h1 = fmaxf(acc[mt][nt][1] + bc1, 0.f);
                    float h2 = fmaxf(acc[mt][nt][2] + bc0, 0.f);
                    float h3 = fmaxf(acc[mt][nt][3] + bc1, 0.f);
                    sA32[r * 132 + (c >> 1)]       = pack_bf16(h0, h1);
                    sA32[(r + 8) * 132 + (c >> 1)] = pack_bf16(h2, h3);
                    acc[mt][nt][0] = 0.f; acc[mt][nt][1] = 0.f;
                    acc[mt][nt][2] = 0.f; acc[mt][nt][3] = 0.f;
                }
            }
            wimg = g_w4b;
            __syncthreads();
        }
    }

    // epilogue2: pf5 = relu(acc + b4) -> atomicMax scatter into g_vox2
#pragma unroll
    for (int mt = 0; mt < 2; mt++) {
        int lr = wm * 32 + mt * 16 + g;
        int pt0 = row0 + lr, pt1 = pt0 + 8;
        int vr0 = svx[lr], vr1 = svx[lr + 8];
        bool ok0 = pt0 < n, ok1 = pt1 < n;
        float* d0 = g_vox2 + (size_t)vr0 * 256;
        float* d1 = g_vox2 + (size_t)vr1 * 256;
#pragma unroll
        for (int nt = 0; nt < 8; nt++) {
            int c = wn * 64 + nt * 8 + 2 * t4;
            float bc0 = __ldg(b4 + c), bc1 = __ldg(b4 + c + 1);
            if (ok0) {
                amax_pos(d0 + c,     acc[mt][nt][0] + bc0);
                amax_pos(d0 + c + 1, acc[mt][nt][1] + bc1);
            }
            if (ok1) {
                amax_pos(d1 + c,     acc[mt][nt][2] + bc0);
                amax_pos(d1 + c + 1, acc[mt][nt][3] + bc1);
            }
        }
    }
}

// ---------------------------------------------------------------------------
// Output GEMM via mma tf32 (unchanged from R7)
// ---------------------------------------------------------------------------
#define SA_ST 260
#define SB_ST 264
#define SC_SMEM ((128 * SA_ST + 2 * 32 * SB_ST + 128) * 4)

__global__ __launch_bounds__(512) void gemm_out_mma(
    const float* __restrict__ A, const float* __restrict__ bias,
    float* __restrict__ out, int M)
{
    extern __shared__ float sm[];
    float* sA = sm;
    float* sB = sm + 128 * SA_ST;

    int t = threadIdx.x;
    int lane = t & 31, wid = t >> 5;
    int g = lane >> 2, t4 = lane & 3;
    int wm = wid & 3, wn = wid >> 2;
    int row0 = blockIdx.x * 128;

    {
        int p = t >> 2, q = t & 3;
        int cp = min(row0 + p, M - 1);
        const float4* src = (const float4*)(A + (size_t)cp * 256 + q * 64);
        float4* dst = (float4*)(sA + p * SA_ST + q * 64);
#pragma unroll
        for (int j = 0; j < 16; j++) {
            float4 v = src[j];
            v.x = tf32f(v.x); v.y = tf32f(v.y);
            v.z = tf32f(v.z); v.w = tf32f(v.w);
            dst[j] = v;
        }
    }

    float acc[2][8][4];
#pragma unroll
    for (int mt = 0; mt < 2; mt++)
#pragma unroll
        for (int nt = 0; nt < 8; nt++)
#pragma unroll
            for (int j = 0; j < 4; j++) acc[mt][nt][j] = 0.f;

    const float* wimg = (const float*)g_wvt;
    float4 pld[4];
    {
        const float4* ws = (const float4*)wimg;
#pragma unroll
        for (int i = 0; i < 4; i++) pld[i] = ws[t + i * 512];
#pragma unroll
        for (int i = 0; i < 4; i++) {
            int e = t + i * 512;
            int k = e >> 6, n4 = e & 63;
            *(float4*)(sB + k * SB_ST + n4 * 4) = pld[i];
        }
    }
    __syncthreads();

#pragma unroll 1
    for (int kc = 0; kc < 8; kc++) {
        if (kc < 7) {
            const float4* ws = (const float4*)(wimg + (kc + 1) * 8192);
#pragma unroll
            for (int i = 0; i < 4; i++) pld[i] = ws[t + i * 512];
        }
        const float* bufB = sB + (kc & 1) * 32 * SB_ST;
#pragma unroll
        for (int k8 = 0; k8 < 4; k8++) {
            int k0 = kc * 32 + k8 * 8;
            uint32_t a[2][4];
#pragma unroll
            for (int mt = 0; mt < 2; mt++) {
                const float* ap = sA + (wm * 32 + mt * 16 + g) * SA_ST + k0 + t4;
                a[mt][0] = __float_as_uint(ap[0]);
                a[mt][1] = __float_as_uint(ap[8 * SA_ST]);
                a[mt][2] = __float_as_uint(ap[4]);
                a[mt][3] = __float_as_uint(ap[8 * SA_ST + 4]);
            }
#pragma unroll
            for (int nt = 0; nt < 8; nt++) {
                const float* bp = bufB + (k8 * 8 + t4) * SB_ST + wn * 64 + nt * 8 + g;
                uint32_t b0 = __float_as_uint(bp[0]);
                uint32_t b1 = __float_as_uint(bp[4 * SB_ST]);
#pragma unroll
                for (int mt = 0; mt < 2; mt++) {
                    asm volatile(
                        "mma.sync.aligned.m16n8k8.row.col.f32.tf32.tf32.f32 "
                        "{%0,%1,%2,%3},{%4,%5,%6,%7},{%8,%9},{%0,%1,%2,%3};"
                        : "+f"(acc[mt][nt][0]), "+f"(acc[mt][nt][1]),
                          "+f"(acc[mt][nt][2]), "+f"(acc[mt][nt][3])
                        : "r"(a[mt][0]), "r"(a[mt][1]), "r"(a[mt][2]), "r"(a[mt][3]),
                          "r"(b0), "r"(b1));
                }
            }
        }
        __syncthreads();
        if (kc < 7) {
            float* nb = sB + ((kc + 1) & 1) * 32 * SB_ST;
#pragma unroll
            for (int i = 0; i < 4; i++) {
                int e = t + i * 512;
                int k = e >> 6, n4 = e & 63;
                *(float4*)(nb + k * SB_ST + n4 * 4) = pld[i];
            }
            __syncthreads();
        }
    }

#pragma unroll
    for (int mt = 0; mt < 2; mt++) {
        int lr = wm * 32 + mt * 16 + g;
        int r0 = row0 + lr, r1 = r0 + 8;
#pragma unroll
        for (int nt = 0; nt < 8; nt++) {
            int c = wn * 64 + nt * 8 + 2 * t4;
            float bc0 = __ldg(bias + c), bc1 = __ldg(bias + c + 1);
            if (r0 < M)
                *(float2*)(out + (size_t)r0 * 256 + c) =
                    make_float2(fmaxf(acc[mt][nt][0] + bc0, 0.f), fmaxf(acc[mt][nt][1] + bc1, 0.f));
            if (r1 < M)
                *(float2*)(out + (size_t)r1 * 256 + c) =
                    make_float2(fmaxf(acc[mt][nt][2] + bc0, 0.f), fmaxf(acc[mt][nt][3] + bc1, 0.f));
        }
    }
}

// ---------------------------------------------------------------------------
extern "C" void kernel_launch(void* const* d_in, const int* in_sizes, int n_in,
                              void* d_out, int out_size)
{
    const float* inp  = (const float*)d_in[0];
    const int*   vidx = (const int*)d_in[1];
    int base = (n_in >= 23) ? 3 : 2;
    const float* w1x = (const float*)d_in[base + 0];
    const float* b1x = (const float*)d_in[base + 1];
    const float* w2x = (const float*)d_in[base + 2];
    const float* b2x = (const float*)d_in[base + 3];
    const float* w1r = (const float*)d_in[base + 4];
    const float* b1r = (const float*)d_in[base + 5];
    const float* w2r = (const float*)d_in[base + 6];
    const float* b2r = (const float*)d_in[base + 7];
    const float* wax = (const float*)d_in[base + 8];
    const float* bax = (const float*)d_in[base + 9];
    const float* war = (const float*)d_in[base + 10];
    const float* bar = (const float*)d_in[base + 11];
    const float* wv1 = (const float*)d_in[base + 12];
    const float* bv1 = (const float*)d_in[base + 13];
    const float* w3  = (const float*)d_in[base + 14];
    const float* b3  = (const float*)d_in[base + 15];
    const float* w4  = (const float*)d_in[base + 16];
    const float* b4  = (const float*)d_in[base + 17];
    const float* wv2 = (const float*)d_in[base + 18];
    const float* bv2 = (const float*)d_in[base + 19];

    int n = in_sizes[0] / 6;
    int V = out_size / 256;

    const int G1_SMEM = (128 * 68 + 32 * 128) * 4;

    cudaFuncSetAttribute(stage_a_mma, cudaFuncAttributeMaxDynamicSharedMemorySize, SAM_SMEM);
    cudaFuncSetAttribute(stage_c_bf16, cudaFuncAttributeMaxDynamicSharedMemorySize, SC4_SMEM);
    cudaFuncSetAttribute(gemm_out_mma, cudaFuncAttributeMaxDynamicSharedMemorySize, SC_SMEM);
    cudaFuncSetAttribute(gemm_relu_b16, cudaFuncAttributeMaxDynamicSharedMemorySize, G1_SMEM);

    float *p_vox, *p_vox2, *p_wvt;
    __nv_bfloat16 *p_w3b, *p_w4b, *p_voxfb;
    cudaGetSymbolAddress((void**)&p_vox, g_vox);
    cudaGetSymbolAddress((void**)&p_voxfb, g_voxfb);
    cudaGetSymbolAddress((void**)&p_vox2, g_vox2);
    cudaGetSymbolAddress((void**)&p_w3b, g_w3b);
    cudaGetSymbolAddress((void**)&p_w4b, g_w4b);
    cudaGetSymbolAddress((void**)&p_wvt, g_wvt);

    int zb = (V * 256 + 255) / 256;
    zero_k<<<zb, 256>>>(V * 128, V * 256);
    prep_wb<<<320, 256>>>(w3, p_w3b);
    prep_wb<<<320, 256>>>(w4, p_w4b);
    prep_tf32<<<256, 256>>>(wv2, p_wvt);

    stage_a_mma<<<(n + 127) / 128, SAM_THREADS, SAM_SMEM>>>(
        inp, vidx, n, w1x, b1x, w2x, b2x, w1r, b1r, w2r, b2r, wax, bax, war, bar);

    gemm_relu_b16<<<(V + 63) / 64, 256, G1_SMEM>>>(p_vox, wv1, bv1, p_voxfb, V);

    stage_c_bf16<<<(n + 63) / 64, 256, SC4_SMEM>>>(vidx, n, b3, b4);

    gemm_out_mma<<<(V + 127) / 128, 512, SC_SMEM>>>(p_vox2, bv2, (float*)d_out, V);
}

// round 9
// speedup vs baseline: 1.9244x; 1.0907x over previous
#include <cuda_runtime.h>
#include <cuda_bf16.h>
#include <cstdint>
#include <math.h>

#define MAXN 500000
#define MAXV 50000

// ---- scratch (static __device__ arrays; allocation-free) ----
__device__ __align__(128) __nv_bfloat16 g_pf2b[(size_t)MAXN * 128];   // pf2 bf16
__device__ __align__(128) float g_vox[(size_t)MAXV * 128];
__device__ __align__(128) __nv_bfloat16 g_voxfb[(size_t)MAXV * 128];  // voxf bf16
__device__ __align__(128) float g_vox2[(size_t)MAXV * 256];
__device__ __align__(128) __nv_bfloat16 g_w3b[81920];   // w3 blocked bf16 [8][256][40]
__device__ __align__(128) __nv_bfloat16 g_w4b[81920];   // w4 blocked bf16
__device__ __align__(128) __nv_bfloat16 g_wvb[81920];   // wv2 blocked bf16 [8][256][40]
__device__ __align__(128) __nv_bfloat16 g_wv1b[20480];  // wv1 blocked bf16 [4][128][40]

__device__ __forceinline__ void amax_pos(float* addr, float v) {
    if (v > 0.f) atomicMax((int*)addr, __float_as_int(v));
}

__device__ __forceinline__ uint32_t f2tf32(float f) {
    uint32_t r;
    asm("cvt.rna.tf32.f32 %0, %1;" : "=r"(r) : "f"(f));
    return r;
}
__device__ __forceinline__ float tf32f(float f) { return __uint_as_float(f2tf32(f)); }

__device__ __forceinline__ uint32_t pack_bf16(float a, float b) {
    __nv_bfloat162 h = __floats2bfloat162_rn(a, b);
    uint32_t r;
    memcpy(&r, &h, 4);
    return r;
}

__device__ __forceinline__ uint32_t smem_u32(const void* p) {
    return (uint32_t)__cvta_generic_to_shared(p);
}
__device__ __forceinline__ void cp_async16(uint32_t dst, const void* src) {
    asm volatile("cp.async.cg.shared.global [%0], [%1], 16;" :: "r"(dst), "l"(src));
}
#define CP_COMMIT() asm volatile("cp.async.commit_group;" ::: "memory")
#define CP_WAIT0()  asm volatile("cp.async.wait_group 0;" ::: "memory")

__device__ __forceinline__ void ldsm4(uint32_t& r0, uint32_t& r1, uint32_t& r2,
                                      uint32_t& r3, uint32_t addr) {
    asm volatile("ldmatrix.sync.aligned.m8n8.x4.shared.b16 {%0,%1,%2,%3}, [%4];"
                 : "=r"(r0), "=r"(r1), "=r"(r2), "=r"(r3) : "r"(addr));
}

__device__ __forceinline__ void mma_bf16(float acc[4], uint32_t a0, uint32_t a1,
                                         uint32_t a2, uint32_t a3, uint32_t b0, uint32_t b1) {
    asm volatile(
        "mma.sync.aligned.m16n8k16.row.col.f32.bf16.bf16.f32 "
        "{%0,%1,%2,%3},{%4,%5,%6,%7},{%8,%9},{%0,%1,%2,%3};"
        : "+f"(acc[0]), "+f"(acc[1]), "+f"(acc[2]), "+f"(acc[3])
        : "r"(a0), "r"(a1), "r"(a2), "r"(a3), "r"(b0), "r"(b1));
}

// ---------------------------------------------------------------------------
__global__ void zero_k(int na, int nb) {
    int i = blockIdx.x * blockDim.x + threadIdx.x;
    int stride = gridDim.x * blockDim.x;
    for (int j = i; j < nb; j += stride) {
        if (j < na) g_vox[j] = 0.f;
        g_vox2[j] = 0.f;
    }
}

// blocked bf16 image builder: w [k][NCOL] row-major -> [kc][NCOL][40]
__device__ __forceinline__ void blk_one(const float* __restrict__ w,
                                        __nv_bfloat16* __restrict__ d, int j, int NCOL) {
    int per = NCOL * 40;
    int kc = j / per, rem = j % per, nn = rem / 40, kl = rem % 40;
    float v = (kl < 32) ? w[(size_t)(kc * 32 + kl) * NCOL + nn] : 0.f;
    d[j] = __float2bfloat16(v);
}

__global__ void prep_all(const float* __restrict__ w3, const float* __restrict__ w4,
                         const float* __restrict__ wv2, const float* __restrict__ wv1) {
    int i = blockIdx.x * blockDim.x + threadIdx.x;
    if (i < 81920) blk_one(w3, g_w3b, i, 256);
    else if (i < 163840) blk_one(w4, g_w4b, i - 81920, 256);
    else if (i < 245760) blk_one(wv2, g_wvb, i - 163840, 256);
    else if (i < 266240) blk_one(wv1, g_wv1b, i - 245760, 128);
}

// ---------------------------------------------------------------------------
// warp micro-GEMM helper: [16x64]@[64x32] tf32, A stride 68, B stride 40
// ---------------------------------------------------------------------------
__device__ __forceinline__ void gemm64x32(const float* __restrict__ As,
                                          const float* __restrict__ Bt,
                                          int wr, int g, int t4, float acc[4][4]) {
#pragma unroll
    for (int k8 = 0; k8 < 8; k8++) {
        const float* ap = As + (wr + g) * 68 + k8 * 8 + t4;
        uint32_t a0 = __float_as_uint(ap[0]);
        uint32_t a1 = __float_as_uint(ap[8 * 68]);
        uint32_t a2 = __float_as_uint(ap[4]);
        uint32_t a3 = __float_as_uint(ap[8 * 68 + 4]);
#pragma unroll
        for (int nt = 0; nt < 4; nt++) {
            const float* bp = Bt + (k8 * 8 + t4) * 40 + nt * 8 + g;
            uint32_t b0 = __float_as_uint(bp[0]);
            uint32_t b1 = __float_as_uint(bp[4 * 40]);
            asm volatile(
                "mma.sync.aligned.m16n8k8.row.col.f32.tf32.tf32.f32 "
                "{%0,%1,%2,%3},{%4,%5,%6,%7},{%8,%9},{%0,%1,%2,%3};"
                : "+f"(acc[nt][0]), "+f"(acc[nt][1]), "+f"(acc[nt][2]), "+f"(acc[nt][3])
                : "r"(a0), "r"(a1), "r"(a2), "r"(a3), "r"(b0), "r"(b1));
        }
    }
}

// ---------------------------------------------------------------------------
// Stage A via mma.sync tf32 (unchanged from R8)
// ---------------------------------------------------------------------------
#define SAM_THREADS 256
#define SAM_SMEM (28288 * 4)

__global__ __launch_bounds__(SAM_THREADS) void stage_a_mma(
    const float* __restrict__ inp, const int* __restrict__ vidx, int n,
    const float* __restrict__ w1x, const float* __restrict__ b1x,
    const float* __restrict__ w2x, const float* __restrict__ b2x,
    const float* __restrict__ w1r, const float* __restrict__ b1r,
    const float* __restrict__ w2r, const float* __restrict__ b2r,
    const float* __restrict__ wax, const float* __restrict__ bax,
    const float* __restrict__ war, const float* __restrict__ bar)
{
    extern __shared__ float sm[];
    float* sW = sm;
    float* sB = sm + 512;
    float* sA = sm + 10752;
    float* sC = sm + 19456;
    int*   svx = (int*)(sm + 28160);

    int t = threadIdx.x;
    int lane = t & 31, w = t >> 5;
    int g = lane >> 2, t4 = lane & 3;
    int wr = 16 * w;
    int row0 = blockIdx.x * 128;

    for (int i = t; i < 192; i += SAM_THREADS) { sW[i] = w1x[i]; sW[256 + i] = w1r[i]; }
    for (int i = t; i < 64; i += SAM_THREADS)  { sW[192 + i] = b1x[i]; sW[448 + i] = b1r[i]; }
    {
        const float* wsrc[4] = {w2x, w2r, wax, war};
#pragma unroll
        for (int a = 0; a < 4; a++) {
            float* dst = sB + a * 2560;
            const float* s = wsrc[a];
            for (int i = t; i < 2048; i += SAM_THREADS) {
                int k = i >> 5, c = i & 31;
                dst[k * 40 + c] = __uint_as_float(f2tf32(s[i]));
            }
        }
    }
    __syncthreads();

    int p = t >> 1, half = t & 1;
    int cp = min(row0 + p, n - 1);
    if (half == 0) svx[p] = vidx[cp];
    float i0 = inp[(size_t)cp * 6 + 0], i1 = inp[(size_t)cp * 6 + 1], i2 = inp[(size_t)cp * 6 + 2];
    float i3 = inp[(size_t)cp * 6 + 3], i4 = inp[(size_t)cp * 6 + 4], i5 = inp[(size_t)cp * 6 + 5];

    {
        const float* W = sW; const float* B = sW + 192;
        int ob = half * 32;
#pragma unroll 8
        for (int o = 0; o < 32; o++) {
            int oo = ob + o;
            float a = B[oo] + i0 * W[oo] + i1 * W[64 + oo] + i2 * W[128 + oo];
            sA[p * 68 + oo] = tf32f(fmaxf(a, 0.f));
        }
    }
    __syncwarp();

    float fx[4][4];
#pragma unroll
    for (int nt = 0; nt < 4; nt++)
#pragma unroll
        for (int j = 0; j < 4; j++) fx[nt][j] = 0.f;
    gemm64x32(sA, sB, wr, g, t4, fx);
    __syncwarp();

#pragma unroll
    for (int nt = 0; nt < 4; nt++) {
        int c = nt * 8 + 2 * t4;
        float bc0 = __ldg(b2x + c), bc1 = __ldg(b2x + c + 1);
        fx[nt][0] = fmaxf(fx[nt][0] + bc0, 0.f);
        fx[nt][1] = fmaxf(fx[nt][1] + bc1, 0.f);
        fx[nt][2] = fmaxf(fx[nt][2] + bc0, 0.f);
        fx[nt][3] = fmaxf(fx[nt][3] + bc1, 0.f);
        int r = wr + g;
        *(float2*)(sC + r * 68 + c) = make_float2(tf32f(fx[nt][0]), tf32f(fx[nt][1]));
        *(float2*)(sC + (r + 8) * 68 + c) = make_float2(tf32f(fx[nt][2]), tf32f(fx[nt][3]));
    }
    {
        const float* W = sW + 256; const float* B = sW + 448;
        int ob = half * 32;
#pragma unroll 8
        for (int o = 0; o < 32; o++) {
            int oo = ob + o;
            float a = B[oo] + i3 * W[oo] + i4 * W[64 + oo] + i5 * W[128 + oo];
            sA[p * 68 + oo] = tf32f(fmaxf(a, 0.f));
        }
    }
    __syncwarp();

    float fr[4][4];
#pragma unroll
    for (int nt = 0; nt < 4; nt++)
#pragma unroll
        for (int j = 0; j < 4; j++) fr[nt][j] = 0.f;
    gemm64x32(sA, sB + 2560, wr, g, t4, fr);
#pragma unroll
    for (int nt = 0; nt < 4; nt++) {
        int c = nt * 8 + 2 * t4;
        float bc0 = __ldg(b2r + c), bc1 = __ldg(b2r + c + 1);
        fr[nt][0] = fmaxf(fr[nt][0] + bc0, 0.f);
        fr[nt][1] = fmaxf(fr[nt][1] + bc1, 0.f);
        fr[nt][2] = fmaxf(fr[nt][2] + bc0, 0.f);
        fr[nt][3] = fmaxf(fr[nt][3] + bc1, 0.f);
        int r = wr + g;
        *(float2*)(sC + r * 68 + 32 + c) = make_float2(tf32f(fr[nt][0]), tf32f(fr[nt][1]));
        *(float2*)(sC + (r + 8) * 68 + 32 + c) = make_float2(tf32f(fr[nt][2]), tf32f(fr[nt][3]));
    }
    __syncwarp();

    float ax[4][4], ar[4][4];
#pragma unroll
    for (int nt = 0; nt < 4; nt++)
#pragma unroll
        for (int j = 0; j < 4; j++) { ax[nt][j] = 0.f; ar[nt][j] = 0.f; }
    gemm64x32(sC, sB + 2 * 2560, wr, g, t4, ax);
    gemm64x32(sC, sB + 3 * 2560, wr, g, t4, ar);

#pragma unroll
    for (int h2 = 0; h2 < 2; h2++) {
        int r = wr + g + 8 * h2;
        int pt = row0 + r;
        if (pt < n) {
            int vr = svx[r];
            uint32_t* pfr = (uint32_t*)(g_pf2b + (size_t)pt * 128);
            float* vxr = g_vox + (size_t)vr * 128;
#pragma unroll
            for (int nt = 0; nt < 4; nt++) {
                int c = nt * 8 + 2 * t4;
                int j0 = 2 * h2, j1 = 2 * h2 + 1;
                float axa = ax[nt][j0] + __ldg(bax + c);
                float axb = ax[nt][j1] + __ldg(bax + c + 1);
                float ara = ar[nt][j0] + __ldg(bar + c);
                float arb = ar[nt][j1] + __ldg(bar + c + 1);
                float sxa = 1.f / (1.f + __expf(-axa));
                float sxb = 1.f / (1.f + __expf(-axb));
                float sra = 1.f / (1.f + __expf(-ara));
                float srb = 1.f / (1.f + __expf(-arb));
                float fxa = fx[nt][j0], fxb = fx[nt][j1];
                float fra = fr[nt][j0], frb = fr[nt][j1];
                float v1a = fxa * sxa, v1b = fxb * sxb;
                float v3a = fra * sra, v3b = frb * srb;
                int cw = c >> 1;
                pfr[cw]      = pack_bf16(fxa, fxb);
                pfr[16 + cw] = pack_bf16(v1a, v1b);
                pfr[32 + cw] = pack_bf16(fra, frb);
                pfr[48 + cw] = pack_bf16(v3a, v3b);
                amax_pos(vxr + c, fxa);        amax_pos(vxr + c + 1, fxb);
                amax_pos(vxr + 32 + c, v1a);   amax_pos(vxr + 33 + c, v1b);
                amax_pos(vxr + 64 + c, fra);   amax_pos(vxr + 65 + c, frb);
                amax_pos(vxr + 96 + c, v3a);   amax_pos(vxr + 97 + c, v3b);
            }
        }
    }
}

// ---------------------------------------------------------------------------
// Generic bf16 GEMM (stage-c recipe): out[M,NCOL] = relu(A[M,K] @ W + bias)
//   KC = K/32 chunks; NT = n-tiles per warp (NCOL = NT*32);
//   64-row tiles, 256 threads, 2 CTAs/SM, ldmatrix + cp.async double buffer.
//   OUT_BF16: store bf16 (packed) else fp32.
// ---------------------------------------------------------------------------
template <int KC, int NT, bool OUT_BF16>
__global__ __launch_bounds__(256, 2) void gemm_bf16_k(
    const float* __restrict__ A, const __nv_bfloat16* __restrict__ Wimg,
    const float* __restrict__ bias, void* __restrict__ outv, int M)
{
    const int K = KC * 32;
    const int AST = K / 2 + 4;        // u32 row stride (68 / 132)
    const int NCOL = NT * 32;
    const int BCH = NCOL * 20;        // u32 per weight chunk
    const int BCH4 = NCOL * 5;        // float4 per weight chunk
    extern __shared__ uint32_t su[];
    uint32_t* sA32 = su;
    uint32_t* sB32 = su + 64 * AST;
    uint32_t sAu = smem_u32(sA32);
    uint32_t sBu = smem_u32(sB32);
    const uint32_t bufu[2] = {sBu, sBu + (uint32_t)BCH * 4u};

    int t = threadIdx.x;
    int lane = t & 31, wid = t >> 5;
    int g = lane >> 2, t4 = lane & 3;
    int wm = wid & 1, wn = wid >> 1;
    int row0 = blockIdx.x * 64;

    uint32_t aA[2];
#pragma unroll
    for (int mt = 0; mt < 2; mt++)
        aA[mt] = sAu + (uint32_t)(((wm * 32 + mt * 16 + (lane & 15)) * AST + (lane >> 4) * 4) * 4);
    uint32_t bBrel[NT / 2];
    {
        int mat = lane >> 3;
        int nt_off = (mat >> 1) * 8, half = mat & 1;
#pragma unroll
        for (int nt2 = 0; nt2 < NT / 2; nt2++) {
            int row = wn * (NT * 8) + nt2 * 16 + nt_off + (lane & 7);
            bBrel[nt2] = (uint32_t)((row * 20 + half * 4) * 4);
        }
    }

    // prologue: async load weight chunk 0
#pragma unroll
    for (int i = 0; i < (BCH4 + 255) / 256; i++) {
        int e = t + i * 256;
        if (e < BCH4) cp_async16(bufu[0] + (uint32_t)e * 16u, (const float4*)Wimg + e);
    }
    CP_COMMIT();

    // gather A rows -> bf16 smem (4 threads per point)
    {
        int p = t >> 2, q = t & 3;
        int cp = min(row0 + p, M - 1);
        const float4* src = (const float4*)(A + (size_t)cp * K + q * (K / 4));
        uint32_t* dst = sA32 + p * AST + q * (K / 8);
#pragma unroll
        for (int j = 0; j < K / 16; j++) {
            float4 v = src[j];
            dst[2 * j]     = pack_bf16(v.x, v.y);
            dst[2 * j + 1] = pack_bf16(v.z, v.w);
        }
    }

    float acc[2][NT][4];
#pragma unroll
    for (int mt = 0; mt < 2; mt++)
#pragma unroll
        for (int nt = 0; nt < NT; nt++)
#pragma unroll
            for (int j = 0; j < 4; j++) acc[mt][nt][j] = 0.f;

    CP_WAIT0();
    __syncthreads();

#pragma unroll 1
    for (int kc = 0; kc < KC; kc++) {
        if (kc < KC - 1) {
            const float4* ws = (const float4*)(Wimg + (size_t)(kc + 1) * NCOL * 40);
#pragma unroll
            for (int i = 0; i < (BCH4 + 255) / 256; i++) {
                int e = t + i * 256;
                if (e < BCH4) cp_async16(bufu[(kc + 1) & 1] + (uint32_t)e * 16u, ws + e);
            }
            CP_COMMIT();
        }
        uint32_t bbase = bufu[kc & 1];
#pragma unroll
        for (int s = 0; s < 2; s++) {
            uint32_t a[2][4];
            ldsm4(a[0][0], a[0][1], a[0][2], a[0][3], aA[0] + (uint32_t)((kc * 16 + s * 8) * 4));
            ldsm4(a[1][0], a[1][1], a[1][2], a[1][3], aA[1] + (uint32_t)((kc * 16 + s * 8) * 4));
            uint32_t b[NT][2];
#pragma unroll
            for (int nt2 = 0; nt2 < NT / 2; nt2++)
                ldsm4(b[2 * nt2][0], b[2 * nt2][1], b[2 * nt2 + 1][0], b[2 * nt2 + 1][1],
                      bbase + bBrel[nt2] + (uint32_t)(s * 32));
#pragma unroll
            for (int nt = 0; nt < NT; nt++)
#pragma unroll
                for (int mt = 0; mt < 2; mt++)
                    mma_bf16(acc[mt][nt], a[mt][0], a[mt][1], a[mt][2], a[mt][3],
                             b[nt][0], b[nt][1]);
        }
        CP_WAIT0();
        __syncthreads();
    }

#pragma unroll
    for (int mt = 0; mt < 2; mt++) {
        int lr = wm * 32 + mt * 16 + g;
        int r0 = row0 + lr, r1 = r0 + 8;
#pragma unroll
        for (int nt = 0; nt < NT; nt++) {
            int c = wn * (NT * 8) + nt * 8 + 2 * t4;
            float bc0 = __ldg(bias + c), bc1 = __ldg(bias + c + 1);
            float v00 = fmaxf(acc[mt][nt][0] + bc0, 0.f);
            float v01 = fmaxf(acc[mt][nt][1] + bc1, 0.f);
            float v10 = fmaxf(acc[mt][nt][2] + bc0, 0.f);
            float v11 = fmaxf(acc[mt][nt][3] + bc1, 0.f);
            if (OUT_BF16) {
                __nv_bfloat16* ob = (__nv_bfloat16*)outv;
                if (r0 < M) ((uint32_t*)(ob + (size_t)r0 * NCOL))[c >> 1] = pack_bf16(v00, v01);
                if (r1 < M) ((uint32_t*)(ob + (size_t)r1 * NCOL))[c >> 1] = pack_bf16(v10, v11);
            } else {
                float* of = (float*)outv;
                if (r0 < M) *(float2*)(of + (size_t)r0 * NCOL + c) = make_float2(v00, v01);
                if (r1 < M) *(float2*)(of + (size_t)r1 * NCOL + c) = make_float2(v10, v11);
            }
        }
    }
}

// ---------------------------------------------------------------------------
// Stage C (bf16 + ldmatrix, unchanged from R8)
// ---------------------------------------------------------------------------
#define SC4_A_U32   (64 * 132)
#define SC4_B_U32   (2 * 5120)
#define SC4_SMEM    ((SC4_A_U32 + SC4_B_U32 + 64) * 4)

__device__ __forceinline__ void ldBb_async(const __nv_bfloat16* __restrict__ ws,
                                           uint32_t dstu, int t) {
#pragma unroll
    for (int i = 0; i < 5; i++) {
        int e = t + i * 256;
        cp_async16(dstu + (uint32_t)e * 16u, (const float4*)ws + e);
    }
}

__global__ __launch_bounds__(256, 2) void stage_c_bf16(
    const int* __restrict__ vidx, int n,
    const float* __restrict__ b3, const float* __restrict__ b4)
{
    extern __shared__ uint32_t su[];
    uint32_t* sA32 = su;
    uint32_t* sB32 = su + SC4_A_U32;
    int* svx = (int*)(su + SC4_A_U32 + SC4_B_U32);
    uint32_t sAu = smem_u32(sA32);
    uint32_t sBu = smem_u32(sB32);
    const uint32_t bufu[2] = {sBu, sBu + 5120u * 4u};

    int t = threadIdx.x;
    int lane = t & 31, wid = t >> 5;
    int g = lane >> 2, t4 = lane & 3;
    int wm = wid & 1, wn = wid >> 1;
    int row0 = blockIdx.x * 64;

    uint32_t aA[2];
#pragma unroll
    for (int mt = 0; mt < 2; mt++)
        aA[mt] = sAu + (uint32_t)(((wm * 32 + mt * 16 + (lane & 15)) * 132 + (lane >> 4) * 4) * 4);
    uint32_t bBrel[4];
    {
        int mat = lane >> 3;
        int nt_off = (mat >> 1) * 8, half = mat & 1;
#pragma unroll
        for (int nt2 = 0; nt2 < 4; nt2++) {
            int row = wn * 64 + nt2 * 16 + nt_off + (lane & 7);
            bBrel[nt2] = (uint32_t)((row * 20 + half * 4) * 4);
        }
    }

    ldBb_async(g_w3b, bufu[0], t);
    CP_COMMIT();

    {
        int p = t >> 2, q = t & 3;
        int pt = row0 + p;
        int cp = min(pt, n - 1);
        int vr = vidx[cp];
        if (q == 0) svx[p] = vr;
        const uint4* src = (q < 2)
            ? (const uint4*)(g_voxfb + (size_t)vr * 128 + q * 64)
            : (const uint4*)(g_pf2b + (size_t)cp * 128 + (q - 2) * 64);
        uint4* dst = (uint4*)(sA32 + p * 132 + q * 32);
#pragma unroll
        for (int j = 0; j < 8; j++) dst[j] = src[j];
    }

    float acc[2][8][4];
#pragma unroll
    for (int mt = 0; mt < 2; mt++)
#pragma unroll
        for (int nt = 0; nt < 8; nt++)
#pragma unroll
            for (int j = 0; j < 4; j++) acc[mt][nt][j] = 0.f;

    CP_WAIT0();
    __syncthreads();

    const __nv_bfloat16* wimg = g_w3b;

#pragma unroll 1
    for (int gg = 0; gg < 2; gg++) {
#pragma unroll 1
        for (int kc = 0; kc < 8; kc++) {
            if (kc < 7) {
                ldBb_async(wimg + (kc + 1) * 10240, bufu[(kc + 1) & 1], t);
                CP_COMMIT();
            } else if (gg == 0) {
                ldBb_async(g_w4b, bufu[0], t);
                CP_COMMIT();
            }
            uint32_t bbase = bufu[kc & 1];
#pragma unroll
            for (int s = 0; s < 2; s++) {
                uint32_t a[2][4];
                ldsm4(a[0][0], a[0][1], a[0][2], a[0][3], aA[0] + (uint32_t)((kc * 16 + s * 8) * 4));
                ldsm4(a[1][0], a[1][1], a[1][2], a[1][3], aA[1] + (uint32_t)((kc * 16 + s * 8) * 4));
                uint32_t b[8][2];
#pragma unroll
                for (int nt2 = 0; nt2 < 4; nt2++)
                    ldsm4(b[2 * nt2][0], b[2 * nt2][1], b[2 * nt2 + 1][0], b[2 * nt2 + 1][1],
                          bbase + bBrel[nt2] + (uint32_t)(s * 32));
#pragma unroll
                for (int nt = 0; nt < 8; nt++)
#pragma unroll
                    for (int mt = 0; mt < 2; mt++)
                        mma_bf16(acc[mt][nt], a[mt][0], a[mt][1], a[mt][2], a[mt][3],
                                 b[nt][0], b[nt][1]);
            }
            CP_WAIT0();
            __syncthreads();
        }

        if (gg == 0) {
#pragma unroll
            for (int nt = 0; nt < 8; nt++) {
                int c = wn * 64 + nt * 8 + 2 * t4;
                float bc0 = __ldg(b3 + c), bc1 = __ldg(b3 + c + 1);
#pragma unroll
                for (int mt = 0; mt < 2; mt++) {
                    int r = wm * 32 + mt * 16 + g;
                    float h0 = fmaxf(acc[mt][nt][0] + bc0, 0.f);
                    float h1 = fmaxf(acc[mt][nt][1] + bc1, 0.f);
                    float h2 = fmaxf(acc[mt][nt][2] + bc0, 0.f);
                    float h3 = fmaxf(acc[mt][nt][3] + bc1, 0.f);
                    sA32[r * 132 + (c >> 1)]       = pack_bf16(h0, h1);
                    sA32[(r + 8) * 132 + (c >> 1)] = pack_bf16(h2, h3);
                    acc[mt][nt][0] = 0.f; acc[mt][nt][1] = 0.f;
                    acc[mt][nt][2] = 0.f; acc[mt][nt][3] = 0.f;
                }
            }
            wimg = g_w4b;
            __syncthreads();
        }
    }

#pragma unroll
    for (int mt = 0; mt < 2; mt++) {
        int lr = wm * 32 + mt * 16 + g;
        int pt0 = row0 + lr, pt1 = pt0 + 8;
        int vr0 = svx[lr], vr1 = svx[lr + 8];
        bool ok0 = pt0 < n, ok1 = pt1 < n;
        float* d0 = g_vox2 + (size_t)vr0 * 256;
        float* d1 = g_vox2 + (size_t)vr1 * 256;
#pragma unroll
        for (int nt = 0; nt < 8; nt++) {
            int c = wn * 64 + nt * 8 + 2 * t4;
            float bc0 = __ldg(b4 + c), bc1 = __ldg(b4 + c + 1);
            if (ok0) {
                amax_pos(d0 + c,     acc[mt][nt][0] + bc0);
                amax_pos(d0 + c + 1, acc[mt][nt][1] + bc1);
            }
            if (ok1) {
                amax_pos(d1 + c,     acc[mt][nt][2] + bc0);
                amax_pos(d1 + c + 1, acc[mt][nt][3] + bc1);
            }
        }
    }
}

// ---------------------------------------------------------------------------
extern "C" void kernel_launch(void* const* d_in, const int* in_sizes, int n_in,
                              void* d_out, int out_size)
{
    const float* inp  = (const float*)d_in[0];
    const int*   vidx = (const int*)d_in[1];
    int base = (n_in >= 23) ? 3 : 2;
    const float* w1x = (const float*)d_in[base + 0];
    const float* b1x = (const float*)d_in[base + 1];
    const float* w2x = (const float*)d_in[base + 2];
    const float* b2x = (const float*)d_in[base + 3];
    const float* w1r = (const float*)d_in[base + 4];
    const float* b1r = (const float*)d_in[base + 5];
    const float* w2r = (const float*)d_in[base + 6];
    const float* b2r = (const float*)d_in[base + 7];
    const float* wax = (const float*)d_in[base + 8];
    const float* bax = (const float*)d_in[base + 9];
    const float* war = (const float*)d_in[base + 10];
    const float* bar = (const float*)d_in[base + 11];
    const float* wv1 = (const float*)d_in[base + 12];
    const float* bv1 = (const float*)d_in[base + 13];
    const float* w3  = (const float*)d_in[base + 14];
    const float* b3  = (const float*)d_in[base + 15];
    const float* w4  = (const float*)d_in[base + 16];
    const float* b4  = (const float*)d_in[base + 17];
    const float* wv2 = (const float*)d_in[base + 18];
    const float* bv2 = (const float*)d_in[base + 19];

    int n = in_sizes[0] / 6;
    int V = out_size / 256;

    const int G1_SMEM = (64 * 68 + 2 * 2560 + 64) * 4;   // wv1 bf16 gemm
    const int GO_SMEM = (64 * 132 + 2 * 5120 + 64) * 4;  // output bf16 gemm

    cudaFuncSetAttribute(stage_a_mma, cudaFuncAttributeMaxDynamicSharedMemorySize, SAM_SMEM);
    cudaFuncSetAttribute(stage_c_bf16, cudaFuncAttributeMaxDynamicSharedMemorySize, SC4_SMEM);
    cudaFuncSetAttribute(gemm_bf16_k<4, 4, true>, cudaFuncAttributeMaxDynamicSharedMemorySize, G1_SMEM);
    cudaFuncSetAttribute(gemm_bf16_k<8, 8, false>, cudaFuncAttributeMaxDynamicSharedMemorySize, GO_SMEM);

    float *p_vox, *p_vox2;
    __nv_bfloat16 *p_voxfb, *p_wvb, *p_wv1b;
    cudaGetSymbolAddress((void**)&p_vox, g_vox);
    cudaGetSymbolAddress((void**)&p_voxfb, g_voxfb);
    cudaGetSymbolAddress((void**)&p_vox2, g_vox2);
    cudaGetSymbolAddress((void**)&p_wvb, g_wvb);
    cudaGetSymbolAddress((void**)&p_wv1b, g_wv1b);

    int zb = (V * 256 + 255) / 256;
    zero_k<<<zb, 256>>>(V * 128, V * 256);
    prep_all<<<1040, 256>>>(w3, w4, wv2, wv1);

    stage_a_mma<<<(n + 127) / 128, SAM_THREADS, SAM_SMEM>>>(
        inp, vidx, n, w1x, b1x, w2x, b2x, w1r, b1r, w2r, b2r, wax, bax, war, bar);

    gemm_bf16_k<4, 4, true><<<(V + 63) / 64, 256, G1_SMEM>>>(p_vox, p_wv1b, bv1, p_voxfb, V);

    stage_c_bf16<<<(n + 63) / 64, 256, SC4_SMEM>>>(vidx, n, b3, b4);

    gemm_bf16_k<8, 8, false><<<(V + 63) / 64, 256, GO_SMEM>>>(p_vox2, p_wvb, bv2, d_out, V);
}